// round 1
// baseline (speedup 1.0000x reference)
#include <cuda_runtime.h>
#include <math.h>

#define BATCH 8
#define NTOK 16384
#define HGT 128
#define HD 64
#define SCALE 0.125f

// ---------------- scratch (device globals: no runtime allocation allowed) ---
__device__ float g_q[BATCH * 4 * NTOK * HD];      // (b,h,n,d)
__device__ float g_k[BATCH * 4 * NTOK * HD];
__device__ float g_v[BATCH * 4 * NTOK * HD];
__device__ float g_fused[BATCH * NTOK * 256];     // (b, n_patchorder, h*64+d)
__device__ float g_gl0[BATCH * 64 * 2 * 2];       // (b, c, p, p) channel-major
__device__ float g_gl1[BATCH * 64 * 4 * 4];
__device__ float g_gl2[BATCH * 64 * 8 * 8];
__device__ float g_gl3[BATCH * 64 * 16 * 16];

// ---------------- GEMM: C(M x NC) = A(M x 256) @ W(256 x NC), fp32 ----------
// 128x128 block tile, BK=8, 256 threads, 8x8 microtile per thread.
// mode 0: scatter to q layout (out0)
// mode 1: scatter to k/v layout (out0=k, out1=v)
// mode 2: dense out0[r*256+c] = acc + bias[c]
__global__ void __launch_bounds__(256) gemm128(
    const float* __restrict__ A, const float* __restrict__ W, int NC, int mode,
    float* __restrict__ out0, float* __restrict__ out1, const float* __restrict__ bias)
{
    __shared__ float As[8][128];
    __shared__ float Bs[8][128];
    int tid = threadIdx.x;
    int tx = tid & 15, ty = tid >> 4;
    int rowBase = blockIdx.y * 128;
    int colBase = blockIdx.x * 128;

    float acc[8][8];
    #pragma unroll
    for (int i = 0; i < 8; i++)
        #pragma unroll
        for (int j = 0; j < 8; j++) acc[i][j] = 0.f;

    int arow = tid >> 1, acol = (tid & 1) * 4;     // A: 128 rows x 8 cols per tile
    int brow = tid >> 5, bcol = (tid & 31) * 4;    // W: 8 rows x 128 cols per tile
    const float* Aptr = A + (size_t)(rowBase + arow) * 256 + acol;
    const float* Wptr = W + (size_t)brow * NC + colBase + bcol;

    for (int kt = 0; kt < 32; kt++) {
        float4 av = *(const float4*)(Aptr + kt * 8);
        As[acol + 0][arow] = av.x;
        As[acol + 1][arow] = av.y;
        As[acol + 2][arow] = av.z;
        As[acol + 3][arow] = av.w;
        float4 bv = *(const float4*)(Wptr + (size_t)kt * 8 * NC);
        *(float4*)&Bs[brow][bcol] = bv;
        __syncthreads();
        #pragma unroll
        for (int kk = 0; kk < 8; kk++) {
            float a[8], b[8];
            #pragma unroll
            for (int i = 0; i < 8; i++) a[i] = As[kk][ty * 8 + i];
            #pragma unroll
            for (int j = 0; j < 8; j++) b[j] = Bs[kk][tx * 8 + j];
            #pragma unroll
            for (int i = 0; i < 8; i++)
                #pragma unroll
                for (int j = 0; j < 8; j++) acc[i][j] += a[i] * b[j];
        }
        __syncthreads();
    }

    int c0 = colBase + tx * 8;  // 8 consecutive cols, always within one 64-col head
    #pragma unroll
    for (int i = 0; i < 8; i++) {
        int r = rowBase + ty * 8 + i;
        if (mode == 2) {
            float* dst = out0 + (size_t)r * 256 + c0;
            #pragma unroll
            for (int j = 0; j < 8; j++) dst[j] = acc[i][j] + bias[c0 + j];
        } else {
            int bb = r >> 14, n = r & 16383;
            int h = (c0 >> 6) & 3, d = c0 & 63;
            float* basep = out0;
            if (mode == 1 && (c0 >> 8)) basep = out1;
            float* dst = basep + ((size_t)(bb * 4 + h) * NTOK + n) * 64 + d;
            #pragma unroll
            for (int j = 0; j < 8; j++) dst[j] = acc[i][j];
        }
    }
}

// ---------------- windowed attention -----------------------------------------
// One 256-thread CTA owns 256 tokens (WPB = 256/S windows). Thread = one query.
// K/V staged in smem with 68-float row stride. Online softmax, fp32.
#define SM_STRIDE 68
#define SMEM_ATT (256 * SM_STRIDE * 2 * 4)

template <int P>
__global__ void __launch_bounds__(256) win_attn(
    const float* __restrict__ qg, const float* __restrict__ kg,
    const float* __restrict__ vg, float* __restrict__ fused, int head)
{
    constexpr int S = P * P;
    constexpr int WPB = 256 / S;
    constexpr int NPX = HGT / P;
    constexpr int NP = NPX * NPX;
    constexpr int BPB = NP / WPB;

    extern __shared__ float sm[];
    float* Ks = sm;
    float* Vs = sm + 256 * SM_STRIDE;

    int t = threadIdx.x;
    int b = blockIdx.x / BPB;
    int wblk = blockIdx.x % BPB;
    int wl = t / S, pos = t % S;
    int win = wblk * WPB + wl;
    int wy = win / NPX, wx = win % NPX;
    int iy = pos / P, ix = pos % P;
    int tok = (wy * P + iy) * HGT + wx * P + ix;
    unsigned base = (unsigned)((b * 4 + head) * NTOK + tok) * 64;

    float q[64];
    #pragma unroll
    for (int d = 0; d < 64; d += 4) {
        float4 k4 = *(const float4*)(kg + base + d);
        *(float4*)&Ks[t * SM_STRIDE + d] = k4;
        float4 v4 = *(const float4*)(vg + base + d);
        *(float4*)&Vs[t * SM_STRIDE + d] = v4;
        float4 q4 = *(const float4*)(qg + base + d);
        q[d] = q4.x; q[d + 1] = q4.y; q[d + 2] = q4.z; q[d + 3] = q4.w;
    }
    __syncthreads();

    float m = -1e30f, l = 0.f, acc[64];
    #pragma unroll
    for (int d = 0; d < 64; d++) acc[d] = 0.f;

    int krow0 = wl * S;
    for (int k = 0; k < S; k++) {
        const float* kr = &Ks[(krow0 + k) * SM_STRIDE];
        float dot = 0.f;
        #pragma unroll
        for (int d = 0; d < 64; d++) dot += q[d] * kr[d];
        dot *= SCALE;
        const float* vr = &Vs[(krow0 + k) * SM_STRIDE];
        if (dot <= m) {
            float p = __expf(dot - m);
            l += p;
            #pragma unroll
            for (int d = 0; d < 64; d++) acc[d] += p * vr[d];
        } else {
            float f = __expf(m - dot);
            m = dot; l = l * f + 1.f;
            #pragma unroll
            for (int d = 0; d < 64; d++) acc[d] = acc[d] * f + vr[d];
        }
    }
    float inv = 1.f / l;
    float* o = fused + ((size_t)b * NTOK + win * S + pos) * 256 + head * 64;
    #pragma unroll
    for (int d = 0; d < 64; d++) o[d] = acc[d] * inv;
}

// ---------------- per-head window mean + bilinear upsample accumulate --------
// gl layout: (b, c, P, P) channel-major (matches torch reshape scramble).
// Thread index maps d to the fastest axis so fused reads are coalesced.
__global__ void mean_up(const float* __restrict__ fused, const float* __restrict__ glp,
                        float* __restrict__ glo, int P, int head)
{
    int i = blockIdx.x * 256 + threadIdx.x;
    int total = BATCH * 64 * P * P;
    if (i >= total) return;
    int d = i % 64;
    int ix = (i / 64) % P;
    int iy = (i / 64 / P) % P;
    int b = i / (64 * P * P);
    int S = P * P, NPX = HGT / P, NP = NPX * NPX;
    int pos = iy * P + ix;

    const float* fp = fused + (size_t)b * NTOK * 256 + (size_t)pos * 256 + head * 64 + d;
    float s = 0.f;
    for (int w = 0; w < NP; w++) s += fp[(size_t)w * S * 256];
    float val = s * (1.f / NP);

    if (glp) {
        int Pp = P / 2;
        float sy = (iy + 0.5f) * 0.5f - 0.5f;
        float sx = (ix + 0.5f) * 0.5f - 0.5f;
        float fy = floorf(sy), fx = floorf(sx);
        float wy = sy - fy, wx = sx - fx;
        int y0 = (int)fy, x0 = (int)fx;
        int y0c = max(0, min(Pp - 1, y0)), y1c = max(0, min(Pp - 1, y0 + 1));
        int x0c = max(0, min(Pp - 1, x0)), x1c = max(0, min(Pp - 1, x0 + 1));
        const float* gp = glp + (size_t)(b * 64 + d) * Pp * Pp;
        float v = (1.f - wy) * ((1.f - wx) * gp[y0c * Pp + x0c] + wx * gp[y0c * Pp + x1c])
                + wy * ((1.f - wx) * gp[y1c * Pp + x0c] + wx * gp[y1c * Pp + x1c]);
        val += v;
    }
    glo[((size_t)(b * 64 + d) * P + iy) * P + ix] = val;
}

// ---------------- global attention (head 3, p=16) -----------------------------
// 256 shared queries from gl16 (contiguous: gq[t] = gl16_flat[t*64 .. +64]),
// attended against each 256-token window; result ADDED into fused.
__global__ void __launch_bounds__(256) global_attn(
    const float* __restrict__ gl16, const float* __restrict__ kg,
    const float* __restrict__ vg, float* __restrict__ fused)
{
    constexpr int P = 16, NPX = 8, NP = 64;
    extern __shared__ float sm[];
    float* Ks = sm;
    float* Vs = sm + 256 * SM_STRIDE;

    int t = threadIdx.x;
    int b = blockIdx.x / NP;
    int win = blockIdx.x % NP;
    int wy = win / NPX, wx = win % NPX;
    int iy = t / P, ix = t % P;
    int tok = (wy * P + iy) * HGT + wx * P + ix;
    unsigned base = (unsigned)((b * 4 + 3) * NTOK + tok) * 64;

    float q[64];
    const float* gq = gl16 + (size_t)b * 64 * 256 + t * 64;
    #pragma unroll
    for (int d = 0; d < 64; d += 4) {
        float4 k4 = *(const float4*)(kg + base + d);
        *(float4*)&Ks[t * SM_STRIDE + d] = k4;
        float4 v4 = *(const float4*)(vg + base + d);
        *(float4*)&Vs[t * SM_STRIDE + d] = v4;
        float4 q4 = *(const float4*)(gq + d);
        q[d] = q4.x; q[d + 1] = q4.y; q[d + 2] = q4.z; q[d + 3] = q4.w;
    }
    __syncthreads();

    float m = -1e30f, l = 0.f, acc[64];
    #pragma unroll
    for (int d = 0; d < 64; d++) acc[d] = 0.f;

    for (int k = 0; k < 256; k++) {
        const float* kr = &Ks[k * SM_STRIDE];
        float dot = 0.f;
        #pragma unroll
        for (int d = 0; d < 64; d++) dot += q[d] * kr[d];
        dot *= SCALE;
        const float* vr = &Vs[k * SM_STRIDE];
        if (dot <= m) {
            float p = __expf(dot - m);
            l += p;
            #pragma unroll
            for (int d = 0; d < 64; d++) acc[d] += p * vr[d];
        } else {
            float f = __expf(m - dot);
            m = dot; l = l * f + 1.f;
            #pragma unroll
            for (int d = 0; d < 64; d++) acc[d] = acc[d] * f + vr[d];
        }
    }
    float inv = 1.f / l;
    float* o = fused + ((size_t)b * NTOK + win * 256 + t) * 256 + 3 * 64;
    #pragma unroll
    for (int d = 0; d < 64; d++) o[d] += acc[d] * inv;
}

// ---------------- launch ------------------------------------------------------
extern "C" void kernel_launch(void* const* d_in, const int* in_sizes, int n_in,
                              void* d_out, int out_size)
{
    (void)in_sizes; (void)n_in; (void)out_size;
    const float* x     = (const float*)d_in[0];
    const float* Wq    = (const float*)d_in[1];
    const float* Wkv   = (const float*)d_in[2];
    const float* Wproj = (const float*)d_in[3];
    const float* bproj = (const float*)d_in[4];
    float* out = (float*)d_out;

    float *qp, *kp, *vp, *fp, *gl0, *gl1, *gl2, *gl3;
    cudaGetSymbolAddress((void**)&qp, g_q);
    cudaGetSymbolAddress((void**)&kp, g_k);
    cudaGetSymbolAddress((void**)&vp, g_v);
    cudaGetSymbolAddress((void**)&fp, g_fused);
    cudaGetSymbolAddress((void**)&gl0, g_gl0);
    cudaGetSymbolAddress((void**)&gl1, g_gl1);
    cudaGetSymbolAddress((void**)&gl2, g_gl2);
    cudaGetSymbolAddress((void**)&gl3, g_gl3);

    cudaFuncSetAttribute(win_attn<2>,  cudaFuncAttributeMaxDynamicSharedMemorySize, SMEM_ATT);
    cudaFuncSetAttribute(win_attn<4>,  cudaFuncAttributeMaxDynamicSharedMemorySize, SMEM_ATT);
    cudaFuncSetAttribute(win_attn<8>,  cudaFuncAttributeMaxDynamicSharedMemorySize, SMEM_ATT);
    cudaFuncSetAttribute(win_attn<16>, cudaFuncAttributeMaxDynamicSharedMemorySize, SMEM_ATT);
    cudaFuncSetAttribute(global_attn,  cudaFuncAttributeMaxDynamicSharedMemorySize, SMEM_ATT);

    // QKV projections
    gemm128<<<dim3(2, 1024), 256>>>(x, Wq, 256, 0, qp, nullptr, nullptr);
    gemm128<<<dim3(4, 1024), 256>>>(x, Wkv, 512, 1, kp, vp, nullptr);

    // Windowed attention per head
    win_attn<2> <<<512, 256, SMEM_ATT>>>(qp, kp, vp, fp, 0);
    win_attn<4> <<<512, 256, SMEM_ATT>>>(qp, kp, vp, fp, 1);
    win_attn<8> <<<512, 256, SMEM_ATT>>>(qp, kp, vp, fp, 2);
    win_attn<16><<<512, 256, SMEM_ATT>>>(qp, kp, vp, fp, 3);

    // Hierarchical global feature (mean over windows + 2x bilinear accumulate)
    mean_up<<<(BATCH * 64 * 4   + 255) / 256, 256>>>(fp, nullptr, gl0, 2, 0);
    mean_up<<<(BATCH * 64 * 16  + 255) / 256, 256>>>(fp, gl0, gl1, 4, 1);
    mean_up<<<(BATCH * 64 * 64  + 255) / 256, 256>>>(fp, gl1, gl2, 8, 2);
    mean_up<<<(BATCH * 64 * 256 + 255) / 256, 256>>>(fp, gl2, gl3, 16, 3);

    // Global attention on head 3 (adds into fused)
    global_attn<<<512, 256, SMEM_ATT>>>(gl3, kp, vp, fp);

    // Output projection + bias
    gemm128<<<dim3(2, 1024), 256>>>(fp, Wproj, 256, 2, out, nullptr, bproj);
}

// round 3
// speedup vs baseline: 1.4361x; 1.4361x over previous
#include <cuda_runtime.h>
#include <cuda_bf16.h>
#include <cstdint>
#include <math.h>

#define BATCH 8
#define NTOK 16384
#define MTOT (BATCH * NTOK)   // 131072
#define HGT 128
#define SCALE 0.125f

// ---------------- scratch (device globals) ----------------------------------
__device__ float g_q[BATCH * 4 * NTOK * 64];
__device__ float g_k[BATCH * 4 * NTOK * 64];
__device__ float g_v[BATCH * 4 * NTOK * 64];
__device__ float g_fused[BATCH * NTOK * 256];
__device__ float g_gl0[BATCH * 64 * 2 * 2];
__device__ float g_gl1[BATCH * 64 * 4 * 4];
__device__ float g_gl2[BATCH * 64 * 8 * 8];
__device__ float g_gl3[BATCH * 64 * 16 * 16];

__device__ __nv_bfloat16 g_xh[MTOT * 256];
__device__ __nv_bfloat16 g_xl[MTOT * 256];
__device__ __nv_bfloat16 g_fh[MTOT * 256];
__device__ __nv_bfloat16 g_fl[MTOT * 256];
__device__ __nv_bfloat16 g_wqh[256 * 256],  g_wql[256 * 256];
__device__ __nv_bfloat16 g_wkvh[512 * 256], g_wkvl[512 * 256];
__device__ __nv_bfloat16 g_wph[256 * 256],  g_wpl[256 * 256];

// ---------------- helpers ----------------------------------------------------
__device__ __forceinline__ uint32_t smem_u32(const void* p) {
    uint32_t a;
    asm("{ .reg .u64 t; cvta.to.shared.u64 t, %1; cvt.u32.u64 %0, t; }" : "=r"(a) : "l"(p));
    return a;
}
__device__ __forceinline__ void cp_async16(uint32_t dst, const void* src) {
    asm volatile("cp.async.cg.shared.global [%0], [%1], 16;" :: "r"(dst), "l"(src) : "memory");
}
#define CP_COMMIT() asm volatile("cp.async.commit_group;" ::: "memory")
#define CP_WAIT(n)  asm volatile("cp.async.wait_group %0;" :: "n"(n) : "memory")

__device__ __forceinline__ void ldm_x4(uint32_t* r, uint32_t addr) {
    asm volatile("ldmatrix.sync.aligned.m8n8.x4.shared.b16 {%0,%1,%2,%3}, [%4];"
        : "=r"(r[0]), "=r"(r[1]), "=r"(r[2]), "=r"(r[3]) : "r"(addr));
}
__device__ __forceinline__ void mma16816(float* c, const uint32_t* a, uint32_t b0, uint32_t b1) {
    asm volatile(
        "mma.sync.aligned.m16n8k16.row.col.f32.bf16.bf16.f32 "
        "{%0,%1,%2,%3}, {%4,%5,%6,%7}, {%8,%9}, {%0,%1,%2,%3};"
        : "+f"(c[0]), "+f"(c[1]), "+f"(c[2]), "+f"(c[3])
        : "r"(a[0]), "r"(a[1]), "r"(a[2]), "r"(a[3]), "r"(b0), "r"(b1));
}

// ---------------- fp32 -> bf16 hi/lo split -----------------------------------
__global__ void split_bf16(const float* __restrict__ in, __nv_bfloat16* __restrict__ h,
                           __nv_bfloat16* __restrict__ l, int n4)
{
    int i = blockIdx.x * 256 + threadIdx.x;
    if (i >= n4) return;
    float4 v = ((const float4*)in)[i];
    __nv_bfloat16 h0 = __float2bfloat16(v.x), h1 = __float2bfloat16(v.y);
    __nv_bfloat16 h2 = __float2bfloat16(v.z), h3 = __float2bfloat16(v.w);
    __nv_bfloat16 l0 = __float2bfloat16(v.x - __bfloat162float(h0));
    __nv_bfloat16 l1 = __float2bfloat16(v.y - __bfloat162float(h1));
    __nv_bfloat16 l2 = __float2bfloat16(v.z - __bfloat162float(h2));
    __nv_bfloat16 l3 = __float2bfloat16(v.w - __bfloat162float(h3));
    ((__nv_bfloat162*)h)[2 * i]     = __nv_bfloat162(h0, h1);
    ((__nv_bfloat162*)h)[2 * i + 1] = __nv_bfloat162(h2, h3);
    ((__nv_bfloat162*)l)[2 * i]     = __nv_bfloat162(l0, l1);
    ((__nv_bfloat162*)l)[2 * i + 1] = __nv_bfloat162(l2, l3);
}

// weight transpose + split: out[n*256+k] = split(W[k*N+n]); K fixed at 256
__global__ void wsplit(const float* __restrict__ W, __nv_bfloat16* __restrict__ th,
                       __nv_bfloat16* __restrict__ tl, int N)
{
    int i = blockIdx.x * 256 + threadIdx.x;
    int k = i & 255, n = i >> 8;
    if (n >= N) return;
    float w = W[(size_t)k * N + n];
    __nv_bfloat16 h = __float2bfloat16(w);
    th[i] = h;
    tl[i] = __float2bfloat16(w - __bfloat162float(h));
}

// ---------------- mma.sync GEMM: (M x 256) @ (256 x NC) ----------------------
// CTA 128x64, BK=32, 8 warps (4Mx2N), warp tile 32x32 = 2x4 m16n8k16 tiles.
// A/B in bf16 hi/lo split; D = AhBh + AhBl + AlBh.
// smem per stage: Ah(128x32,pad40) Al Bh(64x32,pad40) Bl; double-buffered.
// MODE 0: scatter q; 1: scatter k/v; 2: dense + bias.
#define RS 40                      // padded row stride in bf16 elems (80B)
#define A_BYTES (128 * RS * 2)     // 10240
#define B_BYTES (64 * RS * 2)      // 5120
#define STAGE_BYTES (2 * A_BYTES + 2 * B_BYTES)  // 30720
#define GEMM_SMEM (2 * STAGE_BYTES)              // 61440

template <int MODE>
__global__ void __launch_bounds__(256) gemm_mma(
    const __nv_bfloat16* __restrict__ Ah, const __nv_bfloat16* __restrict__ Al,
    const __nv_bfloat16* __restrict__ Bh, const __nv_bfloat16* __restrict__ Bl,
    float* __restrict__ out0, float* __restrict__ out1, const float* __restrict__ bias)
{
    extern __shared__ char smc[];
    uint32_t smb = smem_u32(smc);
    int tid = threadIdx.x, wid = tid >> 5, lane = tid & 31;
    int warpM = wid & 3, warpN = wid >> 2;
    int rowBase = blockIdx.y * 128;
    int colBase = blockIdx.x * 64;

    const __nv_bfloat16* aH = Ah + (size_t)rowBase * 256;
    const __nv_bfloat16* aL = Al + (size_t)rowBase * 256;
    const __nv_bfloat16* bH = Bh + (size_t)colBase * 256;
    const __nv_bfloat16* bL = Bl + (size_t)colBase * 256;

    // per-thread load slots
    int arow0 = tid >> 2, ac0 = (tid & 3);          // A: chunk (row, c) tid -> 2 chunks
    int arow1 = (tid + 256) >> 2, ac1 = ((tid + 256) & 3);
    int brow = tid >> 2, bc = tid & 3;              // B: 64 rows x 4 chunks = 256

    auto issue_stage = [&](int kt, int buf) {
        uint32_t base = smb + buf * STAGE_BYTES;
        size_t asrc0 = (size_t)arow0 * 256 + kt * 32 + ac0 * 8;
        size_t asrc1 = (size_t)arow1 * 256 + kt * 32 + ac1 * 8;
        uint32_t ad0 = base + arow0 * 80 + ac0 * 16;
        uint32_t ad1 = base + arow1 * 80 + ac1 * 16;
        cp_async16(ad0, aH + asrc0);
        cp_async16(ad1, aH + asrc1);
        cp_async16(ad0 + A_BYTES, aL + asrc0);
        cp_async16(ad1 + A_BYTES, aL + asrc1);
        size_t bsrc = (size_t)brow * 256 + kt * 32 + bc * 8;
        uint32_t bd = base + 2 * A_BYTES + brow * 80 + bc * 16;
        cp_async16(bd, bH + bsrc);
        cp_async16(bd + B_BYTES, bL + bsrc);
        CP_COMMIT();
    };

    float acc[2][4][4];
    #pragma unroll
    for (int mi = 0; mi < 2; mi++)
        #pragma unroll
        for (int ni = 0; ni < 4; ni++)
            #pragma unroll
            for (int j = 0; j < 4; j++) acc[mi][ni][j] = 0.f;

    issue_stage(0, 0);

    // ldmatrix lane address components
    int aRowL = warpM * 32 + (lane & 15);
    int aColL = (lane >> 4) * 16;                 // bytes within 16-elem k group
    int bRowL = (lane & 7) + ((lane >> 4) & 1) * 8;
    int bColL = ((lane >> 3) & 1) * 16;

    for (int kt = 0; kt < 8; kt++) {
        int buf = kt & 1;
        if (kt + 1 < 8) issue_stage(kt + 1, buf ^ 1);
        if (kt + 1 < 8) { CP_WAIT(1); } else { CP_WAIT(0); }
        __syncthreads();

        uint32_t sbase = smb + buf * STAGE_BYTES;
        uint32_t af[2][2][2][4];   // [split][mi][kk][4]
        uint32_t bf[2][2][2][4];   // [split][nPair][kk][4]
        #pragma unroll
        for (int sp = 0; sp < 2; sp++) {
            uint32_t abase = sbase + sp * A_BYTES;
            uint32_t bbase = sbase + 2 * A_BYTES + sp * B_BYTES;
            #pragma unroll
            for (int kk = 0; kk < 2; kk++) {
                #pragma unroll
                for (int mi = 0; mi < 2; mi++)
                    ldm_x4(af[sp][mi][kk],
                           abase + (aRowL + mi * 16) * 80 + kk * 32 + aColL);
                // one nPair covers the 32-wide warp N extent (2 pairs)
                #pragma unroll
                for (int np = 0; np < 2; np++)
                    ldm_x4(bf[sp][np][kk],
                           bbase + (warpN * 32 + np * 16 + bRowL) * 80 + kk * 32 + bColL);
            }
        }
        // three split passes: (h,h), (h,l), (l,h)
        #pragma unroll
        for (int pass = 0; pass < 3; pass++) {
            int sa = (pass == 2) ? 1 : 0;
            int sb = (pass == 1) ? 1 : 0;
            #pragma unroll
            for (int kk = 0; kk < 2; kk++)
                #pragma unroll
                for (int mi = 0; mi < 2; mi++)
                    #pragma unroll
                    for (int ni = 0; ni < 4; ni++) {
                        const uint32_t* bb = bf[sb][ni >> 1][kk];
                        mma16816(acc[mi][ni], af[sa][mi][kk],
                                 bb[(ni & 1) * 2], bb[(ni & 1) * 2 + 1]);
                    }
        }
        __syncthreads();
    }

    // epilogue
    #pragma unroll
    for (int mi = 0; mi < 2; mi++) {
        int r0 = rowBase + warpM * 32 + mi * 16 + (lane >> 2);
        #pragma unroll
        for (int ni = 0; ni < 4; ni++) {
            int c = colBase + warpN * 32 + ni * 8 + (lane & 3) * 2;
            float2 v0 = make_float2(acc[mi][ni][0], acc[mi][ni][1]);
            float2 v1 = make_float2(acc[mi][ni][2], acc[mi][ni][3]);
            if (MODE == 2) {
                v0.x += bias[c]; v0.y += bias[c + 1];
                v1.x += bias[c]; v1.y += bias[c + 1];
                *(float2*)(out0 + (size_t)r0 * 256 + c) = v0;
                *(float2*)(out0 + (size_t)(r0 + 8) * 256 + c) = v1;
            } else {
                int C = c;
                float* basep = out0;
                if (MODE == 1 && C >= 256) { basep = out1; C -= 256; }
                int h = C >> 6, d0 = C & 63;
                int b0i = r0 >> 14, n0 = r0 & 16383;
                int b1i = (r0 + 8) >> 14, n1 = (r0 + 8) & 16383;
                *(float2*)(basep + ((size_t)(b0i * 4 + h) * NTOK + n0) * 64 + d0) = v0;
                *(float2*)(basep + ((size_t)(b1i * 4 + h) * NTOK + n1) * 64 + d0) = v1;
            }
        }
    }
}

// ---------------- windowed attention -----------------------------------------
#define SM_STRIDE 68
#define ATT_SMEM(T) ((T) * SM_STRIDE * 2 * 4)

template <int P, int TOKENS>
__global__ void __launch_bounds__(TOKENS) win_attn(
    const float* __restrict__ qg, const float* __restrict__ kg,
    const float* __restrict__ vg, float* __restrict__ fused, int head)
{
    constexpr int S = P * P;
    constexpr int WPB = TOKENS / S;
    constexpr int NPX = HGT / P;
    constexpr int NP = NPX * NPX;
    constexpr int BPB = NP / WPB;

    extern __shared__ float smf[];
    float* Ks = smf;
    float* Vs = smf + TOKENS * SM_STRIDE;

    int t = threadIdx.x;
    int b = blockIdx.x / BPB;
    int wblk = blockIdx.x % BPB;
    int wl = t / S, pos = t % S;
    int win = wblk * WPB + wl;
    int wy = win / NPX, wx = win % NPX;
    int iy = pos / P, ix = pos % P;
    int tok = (wy * P + iy) * HGT + wx * P + ix;
    unsigned base = (unsigned)((b * 4 + head) * NTOK + tok) * 64;

    float q[64];
    #pragma unroll
    for (int d = 0; d < 64; d += 4) {
        *(float4*)&Ks[t * SM_STRIDE + d] = *(const float4*)(kg + base + d);
        *(float4*)&Vs[t * SM_STRIDE + d] = *(const float4*)(vg + base + d);
        float4 q4 = *(const float4*)(qg + base + d);
        q[d] = q4.x; q[d + 1] = q4.y; q[d + 2] = q4.z; q[d + 3] = q4.w;
    }
    __syncthreads();

    float m = -1e30f, l = 0.f, acc[64];
    #pragma unroll
    for (int d = 0; d < 64; d++) acc[d] = 0.f;

    int krow0 = wl * S;
    for (int k = 0; k < S; k++) {
        const float* kr = &Ks[(krow0 + k) * SM_STRIDE];
        float s0 = 0.f, s1 = 0.f, s2 = 0.f, s3 = 0.f;
        #pragma unroll
        for (int d = 0; d < 64; d += 4) {
            s0 += q[d] * kr[d];
            s1 += q[d + 1] * kr[d + 1];
            s2 += q[d + 2] * kr[d + 2];
            s3 += q[d + 3] * kr[d + 3];
        }
        float dot = ((s0 + s1) + (s2 + s3)) * SCALE;
        const float* vr = &Vs[(krow0 + k) * SM_STRIDE];
        if (dot <= m) {
            float p = __expf(dot - m);
            l += p;
            #pragma unroll
            for (int d = 0; d < 64; d++) acc[d] += p * vr[d];
        } else {
            float f = __expf(m - dot);
            m = dot; l = l * f + 1.f;
            #pragma unroll
            for (int d = 0; d < 64; d++) acc[d] = acc[d] * f + vr[d];
        }
    }
    float inv = 1.f / l;
    float* o = fused + ((size_t)b * NTOK + win * S + pos) * 256 + head * 64;
    #pragma unroll
    for (int d = 0; d < 64; d++) o[d] = acc[d] * inv;
}

// ---------------- window mean + bilinear upsample accumulate -----------------
__global__ void mean_up(const float* __restrict__ fused, const float* __restrict__ glp,
                        float* __restrict__ glo, int P, int head)
{
    int i = blockIdx.x * 256 + threadIdx.x;
    int total = BATCH * 64 * P * P;
    if (i >= total) return;
    int d = i % 64;
    int ix = (i / 64) % P;
    int iy = (i / 64 / P) % P;
    int b = i / (64 * P * P);
    int S = P * P, NPX = HGT / P, NP = NPX * NPX;
    int pos = iy * P + ix;

    const float* fp = fused + (size_t)b * NTOK * 256 + (size_t)pos * 256 + head * 64 + d;
    float s = 0.f;
    for (int w = 0; w < NP; w++) s += fp[(size_t)w * S * 256];
    float val = s * (1.f / NP);

    if (glp) {
        int Pp = P / 2;
        float sy = (iy + 0.5f) * 0.5f - 0.5f;
        float sx = (ix + 0.5f) * 0.5f - 0.5f;
        float fy = floorf(sy), fx = floorf(sx);
        float wy = sy - fy, wx = sx - fx;
        int y0 = (int)fy, x0 = (int)fx;
        int y0c = max(0, min(Pp - 1, y0)), y1c = max(0, min(Pp - 1, y0 + 1));
        int x0c = max(0, min(Pp - 1, x0)), x1c = max(0, min(Pp - 1, x0 + 1));
        const float* gp = glp + (size_t)(b * 64 + d) * Pp * Pp;
        float v = (1.f - wy) * ((1.f - wx) * gp[y0c * Pp + x0c] + wx * gp[y0c * Pp + x1c])
                + wy * ((1.f - wx) * gp[y1c * Pp + x0c] + wx * gp[y1c * Pp + x1c]);
        val += v;
    }
    glo[((size_t)(b * 64 + d) * P + iy) * P + ix] = val;
}

// ---------------- global attention (head 3) ----------------------------------
__global__ void __launch_bounds__(256) global_attn(
    const float* __restrict__ gl16, const float* __restrict__ kg,
    const float* __restrict__ vg, float* __restrict__ fused)
{
    constexpr int P = 16, NPX = 8, NP = 64;
    extern __shared__ float smf[];
    float* Ks = smf;
    float* Vs = smf + 256 * SM_STRIDE;

    int t = threadIdx.x;
    int b = blockIdx.x / NP;
    int win = blockIdx.x % NP;
    int wy = win / NPX, wx = win % NPX;
    int iy = t / P, ix = t % P;
    int tok = (wy * P + iy) * HGT + wx * P + ix;
    unsigned base = (unsigned)((b * 4 + 3) * NTOK + tok) * 64;

    float q[64];
    const float* gq = gl16 + (size_t)b * 64 * 256 + t * 64;
    #pragma unroll
    for (int d = 0; d < 64; d += 4) {
        *(float4*)&Ks[t * SM_STRIDE + d] = *(const float4*)(kg + base + d);
        *(float4*)&Vs[t * SM_STRIDE + d] = *(const float4*)(vg + base + d);
        float4 q4 = *(const float4*)(gq + d);
        q[d] = q4.x; q[d + 1] = q4.y; q[d + 2] = q4.z; q[d + 3] = q4.w;
    }
    __syncthreads();

    float m = -1e30f, l = 0.f, acc[64];
    #pragma unroll
    for (int d = 0; d < 64; d++) acc[d] = 0.f;

    for (int k = 0; k < 256; k++) {
        const float* kr = &Ks[k * SM_STRIDE];
        float s0 = 0.f, s1 = 0.f, s2 = 0.f, s3 = 0.f;
        #pragma unroll
        for (int d = 0; d < 64; d += 4) {
            s0 += q[d] * kr[d];
            s1 += q[d + 1] * kr[d + 1];
            s2 += q[d + 2] * kr[d + 2];
            s3 += q[d + 3] * kr[d + 3];
        }
        float dot = ((s0 + s1) + (s2 + s3)) * SCALE;
        const float* vr = &Vs[k * SM_STRIDE];
        if (dot <= m) {
            float p = __expf(dot - m);
            l += p;
            #pragma unroll
            for (int d = 0; d < 64; d++) acc[d] += p * vr[d];
        } else {
            float f = __expf(m - dot);
            m = dot; l = l * f + 1.f;
            #pragma unroll
            for (int d = 0; d < 64; d++) acc[d] = acc[d] * f + vr[d];
        }
    }
    float inv = 1.f / l;
    float* o = fused + ((size_t)b * NTOK + win * 256 + t) * 256 + 3 * 64;
    #pragma unroll
    for (int d = 0; d < 64; d++) o[d] += acc[d] * inv;
}

// ---------------- launch ------------------------------------------------------
extern "C" void kernel_launch(void* const* d_in, const int* in_sizes, int n_in,
                              void* d_out, int out_size)
{
    (void)in_sizes; (void)n_in; (void)out_size;
    const float* x     = (const float*)d_in[0];
    const float* Wq    = (const float*)d_in[1];
    const float* Wkv   = (const float*)d_in[2];
    const float* Wproj = (const float*)d_in[3];
    const float* bproj = (const float*)d_in[4];
    float* out = (float*)d_out;

    float *qp, *kp, *vp, *fp, *gl0, *gl1, *gl2, *gl3;
    __nv_bfloat16 *xh, *xl, *fh, *fl, *wqh, *wql, *wkvh, *wkvl, *wph, *wpl;
    cudaGetSymbolAddress((void**)&qp, g_q);
    cudaGetSymbolAddress((void**)&kp, g_k);
    cudaGetSymbolAddress((void**)&vp, g_v);
    cudaGetSymbolAddress((void**)&fp, g_fused);
    cudaGetSymbolAddress((void**)&gl0, g_gl0);
    cudaGetSymbolAddress((void**)&gl1, g_gl1);
    cudaGetSymbolAddress((void**)&gl2, g_gl2);
    cudaGetSymbolAddress((void**)&gl3, g_gl3);
    cudaGetSymbolAddress((void**)&xh, g_xh);
    cudaGetSymbolAddress((void**)&xl, g_xl);
    cudaGetSymbolAddress((void**)&fh, g_fh);
    cudaGetSymbolAddress((void**)&fl, g_fl);
    cudaGetSymbolAddress((void**)&wqh, g_wqh);
    cudaGetSymbolAddress((void**)&wql, g_wql);
    cudaGetSymbolAddress((void**)&wkvh, g_wkvh);
    cudaGetSymbolAddress((void**)&wkvl, g_wkvl);
    cudaGetSymbolAddress((void**)&wph, g_wph);
    cudaGetSymbolAddress((void**)&wpl, g_wpl);

    cudaFuncSetAttribute(gemm_mma<0>, cudaFuncAttributeMaxDynamicSharedMemorySize, GEMM_SMEM);
    cudaFuncSetAttribute(gemm_mma<1>, cudaFuncAttributeMaxDynamicSharedMemorySize, GEMM_SMEM);
    cudaFuncSetAttribute(gemm_mma<2>, cudaFuncAttributeMaxDynamicSharedMemorySize, GEMM_SMEM);
    cudaFuncSetAttribute((win_attn<2, 128>),  cudaFuncAttributeMaxDynamicSharedMemorySize, ATT_SMEM(128));
    cudaFuncSetAttribute((win_attn<4, 128>),  cudaFuncAttributeMaxDynamicSharedMemorySize, ATT_SMEM(128));
    cudaFuncSetAttribute((win_attn<8, 128>),  cudaFuncAttributeMaxDynamicSharedMemorySize, ATT_SMEM(128));
    cudaFuncSetAttribute((win_attn<16, 256>), cudaFuncAttributeMaxDynamicSharedMemorySize, ATT_SMEM(256));
    cudaFuncSetAttribute(global_attn,         cudaFuncAttributeMaxDynamicSharedMemorySize, ATT_SMEM(256));

    // input / weight splits
    split_bf16<<<(MTOT * 256 / 4 + 255) / 256, 256>>>(x, xh, xl, MTOT * 256 / 4);
    wsplit<<<256, 256>>>(Wq, wqh, wql, 256);
    wsplit<<<512, 256>>>(Wkv, wkvh, wkvl, 512);
    wsplit<<<256, 256>>>(Wproj, wph, wpl, 256);

    // QKV projections on tensor cores (mma.sync)
    gemm_mma<0><<<dim3(4, 1024), 256, GEMM_SMEM>>>(xh, xl, wqh, wql, qp, nullptr, nullptr);
    gemm_mma<1><<<dim3(8, 1024), 256, GEMM_SMEM>>>(xh, xl, wkvh, wkvl, kp, vp, nullptr);

    // windowed attention
    win_attn<2, 128> <<<1024, 128, ATT_SMEM(128)>>>(qp, kp, vp, fp, 0);
    win_attn<4, 128> <<<1024, 128, ATT_SMEM(128)>>>(qp, kp, vp, fp, 1);
    win_attn<8, 128> <<<1024, 128, ATT_SMEM(128)>>>(qp, kp, vp, fp, 2);
    win_attn<16, 256><<<512,  256, ATT_SMEM(256)>>>(qp, kp, vp, fp, 3);

    // hierarchical global feature
    mean_up<<<(BATCH * 64 * 4   + 255) / 256, 256>>>(fp, nullptr, gl0, 2, 0);
    mean_up<<<(BATCH * 64 * 16  + 255) / 256, 256>>>(fp, gl0, gl1, 4, 1);
    mean_up<<<(BATCH * 64 * 64  + 255) / 256, 256>>>(fp, gl1, gl2, 8, 2);
    mean_up<<<(BATCH * 64 * 256 + 255) / 256, 256>>>(fp, gl2, gl3, 16, 3);

    // global attention on head 3 (adds into fused)
    global_attn<<<512, 256, ATT_SMEM(256)>>>(gl3, kp, vp, fp);

    // output projection
    split_bf16<<<(MTOT * 256 / 4 + 255) / 256, 256>>>(fp, fh, fl, MTOT * 256 / 4);
    gemm_mma<2><<<dim3(4, 1024), 256, GEMM_SMEM>>>(fh, fl, wph, wpl, out, nullptr, bproj);
}

// round 4
// speedup vs baseline: 1.5207x; 1.0589x over previous
#include <cuda_runtime.h>
#include <cuda_bf16.h>
#include <cuda_fp16.h>
#include <cstdint>
#include <math.h>

#define BATCH 8
#define NTOK 16384
#define MTOT (BATCH * NTOK)   // 131072
#define HGT 128
#define SCALE 0.125f

// ---------------- scratch (device globals) ----------------------------------
__device__ float g_q[BATCH * 4 * NTOK * 64];
__device__ float g_k[BATCH * 4 * NTOK * 64];
__device__ float g_v[BATCH * 4 * NTOK * 64];
__device__ float g_fused[BATCH * NTOK * 256];
__device__ float g_gl0[BATCH * 64 * 2 * 2];
__device__ float g_gl1[BATCH * 64 * 4 * 4];
__device__ float g_gl2[BATCH * 64 * 8 * 8];
__device__ float g_gl3[BATCH * 64 * 16 * 16];

__device__ __half g_xh[MTOT * 256];
__device__ __half g_xl[MTOT * 256];
__device__ __half g_fh[MTOT * 256];
__device__ __half g_fl[MTOT * 256];
__device__ __half g_wq[256 * 256];
__device__ __half g_wkv[512 * 256];
__device__ __half g_wp[256 * 256];

// ---------------- helpers ----------------------------------------------------
__device__ __forceinline__ uint32_t smem_u32(const void* p) {
    uint32_t a;
    asm("{ .reg .u64 t; cvta.to.shared.u64 t, %1; cvt.u32.u64 %0, t; }" : "=r"(a) : "l"(p));
    return a;
}
__device__ __forceinline__ void cp_async16(uint32_t dst, const void* src) {
    asm volatile("cp.async.cg.shared.global [%0], [%1], 16;" :: "r"(dst), "l"(src) : "memory");
}
#define CP_COMMIT() asm volatile("cp.async.commit_group;" ::: "memory")
#define CP_WAIT(n)  asm volatile("cp.async.wait_group %0;" :: "n"(n) : "memory")

__device__ __forceinline__ void ldm_x4(uint32_t* r, uint32_t addr) {
    asm volatile("ldmatrix.sync.aligned.m8n8.x4.shared.b16 {%0,%1,%2,%3}, [%4];"
        : "=r"(r[0]), "=r"(r[1]), "=r"(r[2]), "=r"(r[3]) : "r"(addr));
}
__device__ __forceinline__ void mma16816(float* c, const uint32_t* a, uint32_t b0, uint32_t b1) {
    asm volatile(
        "mma.sync.aligned.m16n8k16.row.col.f32.f16.f16.f32 "
        "{%0,%1,%2,%3}, {%4,%5,%6,%7}, {%8,%9}, {%0,%1,%2,%3};"
        : "+f"(c[0]), "+f"(c[1]), "+f"(c[2]), "+f"(c[3])
        : "r"(a[0]), "r"(a[1]), "r"(a[2]), "r"(a[3]), "r"(b0), "r"(b1));
}

// ---------------- fp32 -> fp16 hi/lo split -----------------------------------
__global__ void split_fp16(const float* __restrict__ in, __half* __restrict__ h,
                           __half* __restrict__ l, int n4)
{
    int i = blockIdx.x * 256 + threadIdx.x;
    if (i >= n4) return;
    float4 v = ((const float4*)in)[i];
    __half h0 = __float2half(v.x), h1 = __float2half(v.y);
    __half h2 = __float2half(v.z), h3 = __float2half(v.w);
    __half l0 = __float2half(v.x - __half2float(h0));
    __half l1 = __float2half(v.y - __half2float(h1));
    __half l2 = __float2half(v.z - __half2float(h2));
    __half l3 = __float2half(v.w - __half2float(h3));
    ((__half2*)h)[2 * i]     = __halves2half2(h0, h1);
    ((__half2*)h)[2 * i + 1] = __halves2half2(h2, h3);
    ((__half2*)l)[2 * i]     = __halves2half2(l0, l1);
    ((__half2*)l)[2 * i + 1] = __halves2half2(l2, l3);
}

// weight transpose to n-major fp16: out[n*256+k] = W[k*N+n]
__global__ void wsplit(const float* __restrict__ W, __half* __restrict__ th, int N)
{
    int i = blockIdx.x * 256 + threadIdx.x;
    int k = i & 255, n = i >> 8;
    if (n >= N) return;
    th[i] = __float2half(W[(size_t)k * N + n]);
}

// ---------------- mma.sync GEMM: (M x 256) @ (256 x NC) ----------------------
// CTA 128x128, BK=32, 8 warps (4M x 2N), warp tile 32x64 = 2x8 m16n8k16 tiles.
// A in fp16 hi/lo split, B single fp16; D = Ah*B + Al*B. Double-buffered cp.async.
// MODE 0: scatter q; 1: scatter k/v; 2: dense + bias.
#define RS80 80                    // padded row pitch in bytes (40 halfs)
#define A_BYTES (128 * RS80)       // 10240 per split
#define B_BYTES (128 * RS80)       // 10240
#define STAGE_BYTES (2 * A_BYTES + B_BYTES)   // 30720
#define GEMM_SMEM (2 * STAGE_BYTES)           // 61440

template <int MODE>
__global__ void __launch_bounds__(256) gemm_mma(
    const __half* __restrict__ Ah, const __half* __restrict__ Al,
    const __half* __restrict__ B,
    float* __restrict__ out0, float* __restrict__ out1, const float* __restrict__ bias)
{
    extern __shared__ char smc[];
    uint32_t smb = smem_u32(smc);
    int tid = threadIdx.x, wid = tid >> 5, lane = tid & 31;
    int warpM = wid & 3, warpN = wid >> 2;
    int rowBase = blockIdx.y * 128;
    int colBase = blockIdx.x * 128;

    const __half* aH = Ah + (size_t)rowBase * 256;
    const __half* aL = Al + (size_t)rowBase * 256;
    const __half* bP = B + (size_t)colBase * 256;

    // per-thread load slots: 128 rows x 4 16B-chunks per row (64B = 32 halfs)
    int r0s = tid >> 2, c0s = tid & 3;
    int r1s = r0s + 64;

    auto issue_stage = [&](int kt, int buf) {
        uint32_t base = smb + buf * STAGE_BYTES;
        size_t src0 = (size_t)r0s * 256 + kt * 32 + c0s * 8;
        size_t src1 = (size_t)r1s * 256 + kt * 32 + c0s * 8;
        uint32_t d0 = base + r0s * RS80 + c0s * 16;
        uint32_t d1 = base + r1s * RS80 + c0s * 16;
        cp_async16(d0, aH + src0);
        cp_async16(d1, aH + src1);
        cp_async16(d0 + A_BYTES, aL + src0);
        cp_async16(d1 + A_BYTES, aL + src1);
        cp_async16(d0 + 2 * A_BYTES, bP + src0);
        cp_async16(d1 + 2 * A_BYTES, bP + src1);
        CP_COMMIT();
    };

    float acc[2][8][4];
    #pragma unroll
    for (int mi = 0; mi < 2; mi++)
        #pragma unroll
        for (int ni = 0; ni < 8; ni++)
            #pragma unroll
            for (int j = 0; j < 4; j++) acc[mi][ni][j] = 0.f;

    issue_stage(0, 0);

    int aRowL = warpM * 32 + (lane & 15);
    int aColL = (lane >> 4) * 16;
    int bRowL = (lane & 7) + ((lane >> 4) & 1) * 8;
    int bColL = ((lane >> 3) & 1) * 16;

    for (int kt = 0; kt < 8; kt++) {
        int buf = kt & 1;
        if (kt + 1 < 8) issue_stage(kt + 1, buf ^ 1);
        if (kt + 1 < 8) { CP_WAIT(1); } else { CP_WAIT(0); }
        __syncthreads();

        uint32_t sbase = smb + buf * STAGE_BYTES;
        #pragma unroll
        for (int kk = 0; kk < 2; kk++) {
            uint32_t af[2][2][4];
            uint32_t bfr[4][4];
            #pragma unroll
            for (int sp = 0; sp < 2; sp++)
                #pragma unroll
                for (int mi = 0; mi < 2; mi++)
                    ldm_x4(af[sp][mi],
                           sbase + sp * A_BYTES + (aRowL + mi * 16) * RS80 + kk * 32 + aColL);
            #pragma unroll
            for (int np = 0; np < 4; np++)
                ldm_x4(bfr[np],
                       sbase + 2 * A_BYTES + (warpN * 64 + np * 16 + bRowL) * RS80 + kk * 32 + bColL);
            #pragma unroll
            for (int sp = 0; sp < 2; sp++)
                #pragma unroll
                for (int mi = 0; mi < 2; mi++)
                    #pragma unroll
                    for (int ni = 0; ni < 8; ni++)
                        mma16816(acc[mi][ni], af[sp][mi],
                                 bfr[ni >> 1][(ni & 1) * 2], bfr[ni >> 1][(ni & 1) * 2 + 1]);
        }
        __syncthreads();
    }

    // epilogue
    #pragma unroll
    for (int mi = 0; mi < 2; mi++) {
        int r0 = rowBase + warpM * 32 + mi * 16 + (lane >> 2);
        #pragma unroll
        for (int ni = 0; ni < 8; ni++) {
            int c = colBase + warpN * 64 + ni * 8 + (lane & 3) * 2;
            float2 v0 = make_float2(acc[mi][ni][0], acc[mi][ni][1]);
            float2 v1 = make_float2(acc[mi][ni][2], acc[mi][ni][3]);
            if (MODE == 2) {
                v0.x += bias[c]; v0.y += bias[c + 1];
                v1.x += bias[c]; v1.y += bias[c + 1];
                *(float2*)(out0 + (size_t)r0 * 256 + c) = v0;
                *(float2*)(out0 + (size_t)(r0 + 8) * 256 + c) = v1;
            } else {
                int C = c;
                float* basep = out0;
                if (MODE == 1 && C >= 256) { basep = out1; C -= 256; }
                int h = C >> 6, d0 = C & 63;
                int b0i = r0 >> 14, n0 = r0 & 16383;
                int b1i = (r0 + 8) >> 14, n1 = (r0 + 8) & 16383;
                *(float2*)(basep + ((size_t)(b0i * 4 + h) * NTOK + n0) * 64 + d0) = v0;
                *(float2*)(basep + ((size_t)(b1i * 4 + h) * NTOK + n1) * 64 + d0) = v1;
            }
        }
    }
}

// ---------------- windowed attention -----------------------------------------
#define SM_STRIDE 68
#define ATT_SMEM(T) ((T) * SM_STRIDE * 2 * 4)

template <int P, int TOKENS>
__global__ void __launch_bounds__(TOKENS) win_attn(
    const float* __restrict__ qg, const float* __restrict__ kg,
    const float* __restrict__ vg, float* __restrict__ fused, int head)
{
    constexpr int S = P * P;
    constexpr int WPB = TOKENS / S;
    constexpr int NPX = HGT / P;
    constexpr int NP = NPX * NPX;
    constexpr int BPB = NP / WPB;

    extern __shared__ float smf[];
    float* Ks = smf;
    float* Vs = smf + TOKENS * SM_STRIDE;

    int t = threadIdx.x;
    int b = blockIdx.x / BPB;
    int wblk = blockIdx.x % BPB;
    int wl = t / S, pos = t % S;
    int win = wblk * WPB + wl;
    int wy = win / NPX, wx = win % NPX;
    int iy = pos / P, ix = pos % P;
    int tok = (wy * P + iy) * HGT + wx * P + ix;
    unsigned base = (unsigned)((b * 4 + head) * NTOK + tok) * 64;

    float q[64];
    #pragma unroll
    for (int d = 0; d < 64; d += 4) {
        *(float4*)&Ks[t * SM_STRIDE + d] = *(const float4*)(kg + base + d);
        *(float4*)&Vs[t * SM_STRIDE + d] = *(const float4*)(vg + base + d);
        float4 q4 = *(const float4*)(qg + base + d);
        q[d] = q4.x; q[d + 1] = q4.y; q[d + 2] = q4.z; q[d + 3] = q4.w;
    }
    __syncthreads();

    float m = -1e30f, l = 0.f, acc[64];
    #pragma unroll
    for (int d = 0; d < 64; d++) acc[d] = 0.f;

    int krow0 = wl * S;
    for (int k = 0; k < S; k++) {
        const float* kr = &Ks[(krow0 + k) * SM_STRIDE];
        float s0 = 0.f, s1 = 0.f, s2 = 0.f, s3 = 0.f;
        #pragma unroll
        for (int d = 0; d < 64; d += 4) {
            s0 += q[d] * kr[d];
            s1 += q[d + 1] * kr[d + 1];
            s2 += q[d + 2] * kr[d + 2];
            s3 += q[d + 3] * kr[d + 3];
        }
        float dot = ((s0 + s1) + (s2 + s3)) * SCALE;
        const float* vr = &Vs[(krow0 + k) * SM_STRIDE];
        if (dot <= m) {
            float p = __expf(dot - m);
            l += p;
            #pragma unroll
            for (int d = 0; d < 64; d++) acc[d] += p * vr[d];
        } else {
            float f = __expf(m - dot);
            m = dot; l = l * f + 1.f;
            #pragma unroll
            for (int d = 0; d < 64; d++) acc[d] = acc[d] * f + vr[d];
        }
    }
    float inv = 1.f / l;
    float* o = fused + ((size_t)b * NTOK + win * S + pos) * 256 + head * 64;
    #pragma unroll
    for (int d = 0; d < 64; d++) o[d] = acc[d] * inv;
}

// ---------------- window mean + bilinear upsample accumulate -----------------
__global__ void mean_up(const float* __restrict__ fused, const float* __restrict__ glp,
                        float* __restrict__ glo, int P, int head)
{
    int i = blockIdx.x * 256 + threadIdx.x;
    int total = BATCH * 64 * P * P;
    if (i >= total) return;
    int d = i % 64;
    int ix = (i / 64) % P;
    int iy = (i / 64 / P) % P;
    int b = i / (64 * P * P);
    int S = P * P, NPX = HGT / P, NP = NPX * NPX;
    int pos = iy * P + ix;

    const float* fp = fused + (size_t)b * NTOK * 256 + (size_t)pos * 256 + head * 64 + d;
    float s = 0.f;
    for (int w = 0; w < NP; w++) s += fp[(size_t)w * S * 256];
    float val = s * (1.f / NP);

    if (glp) {
        int Pp = P / 2;
        float sy = (iy + 0.5f) * 0.5f - 0.5f;
        float sx = (ix + 0.5f) * 0.5f - 0.5f;
        float fy = floorf(sy), fx = floorf(sx);
        float wy = sy - fy, wx = sx - fx;
        int y0 = (int)fy, x0 = (int)fx;
        int y0c = max(0, min(Pp - 1, y0)), y1c = max(0, min(Pp - 1, y0 + 1));
        int x0c = max(0, min(Pp - 1, x0)), x1c = max(0, min(Pp - 1, x0 + 1));
        const float* gp = glp + (size_t)(b * 64 + d) * Pp * Pp;
        float v = (1.f - wy) * ((1.f - wx) * gp[y0c * Pp + x0c] + wx * gp[y0c * Pp + x1c])
                + wy * ((1.f - wx) * gp[y1c * Pp + x0c] + wx * gp[y1c * Pp + x1c]);
        val += v;
    }
    glo[((size_t)(b * 64 + d) * P + iy) * P + ix] = val;
}

// ---------------- global attention (head 3) ----------------------------------
__global__ void __launch_bounds__(256) global_attn(
    const float* __restrict__ gl16, const float* __restrict__ kg,
    const float* __restrict__ vg, float* __restrict__ fused)
{
    constexpr int P = 16, NPX = 8, NP = 64;
    extern __shared__ float smf[];
    float* Ks = smf;
    float* Vs = smf + 256 * SM_STRIDE;

    int t = threadIdx.x;
    int b = blockIdx.x / NP;
    int win = blockIdx.x % NP;
    int wy = win / NPX, wx = win % NPX;
    int iy = t / P, ix = t % P;
    int tok = (wy * P + iy) * HGT + wx * P + ix;
    unsigned base = (unsigned)((b * 4 + 3) * NTOK + tok) * 64;

    float q[64];
    const float* gq = gl16 + (size_t)b * 64 * 256 + t * 64;
    #pragma unroll
    for (int d = 0; d < 64; d += 4) {
        *(float4*)&Ks[t * SM_STRIDE + d] = *(const float4*)(kg + base + d);
        *(float4*)&Vs[t * SM_STRIDE + d] = *(const float4*)(vg + base + d);
        float4 q4 = *(const float4*)(gq + d);
        q[d] = q4.x; q[d + 1] = q4.y; q[d + 2] = q4.z; q[d + 3] = q4.w;
    }
    __syncthreads();

    float m = -1e30f, l = 0.f, acc[64];
    #pragma unroll
    for (int d = 0; d < 64; d++) acc[d] = 0.f;

    for (int k = 0; k < 256; k++) {
        const float* kr = &Ks[k * SM_STRIDE];
        float s0 = 0.f, s1 = 0.f, s2 = 0.f, s3 = 0.f;
        #pragma unroll
        for (int d = 0; d < 64; d += 4) {
            s0 += q[d] * kr[d];
            s1 += q[d + 1] * kr[d + 1];
            s2 += q[d + 2] * kr[d + 2];
            s3 += q[d + 3] * kr[d + 3];
        }
        float dot = ((s0 + s1) + (s2 + s3)) * SCALE;
        const float* vr = &Vs[k * SM_STRIDE];
        if (dot <= m) {
            float p = __expf(dot - m);
            l += p;
            #pragma unroll
            for (int d = 0; d < 64; d++) acc[d] += p * vr[d];
        } else {
            float f = __expf(m - dot);
            m = dot; l = l * f + 1.f;
            #pragma unroll
            for (int d = 0; d < 64; d++) acc[d] = acc[d] * f + vr[d];
        }
    }
    float inv = 1.f / l;
    float* o = fused + ((size_t)b * NTOK + win * 256 + t) * 256 + 3 * 64;
    #pragma unroll
    for (int d = 0; d < 64; d++) o[d] += acc[d] * inv;
}

// ---------------- launch ------------------------------------------------------
extern "C" void kernel_launch(void* const* d_in, const int* in_sizes, int n_in,
                              void* d_out, int out_size)
{
    (void)in_sizes; (void)n_in; (void)out_size;
    const float* x     = (const float*)d_in[0];
    const float* Wq    = (const float*)d_in[1];
    const float* Wkv   = (const float*)d_in[2];
    const float* Wproj = (const float*)d_in[3];
    const float* bproj = (const float*)d_in[4];
    float* out = (float*)d_out;

    float *qp, *kp, *vp, *fp, *gl0, *gl1, *gl2, *gl3;
    __half *xh, *xl, *fh, *fl, *wq, *wkv, *wp;
    cudaGetSymbolAddress((void**)&qp, g_q);
    cudaGetSymbolAddress((void**)&kp, g_k);
    cudaGetSymbolAddress((void**)&vp, g_v);
    cudaGetSymbolAddress((void**)&fp, g_fused);
    cudaGetSymbolAddress((void**)&gl0, g_gl0);
    cudaGetSymbolAddress((void**)&gl1, g_gl1);
    cudaGetSymbolAddress((void**)&gl2, g_gl2);
    cudaGetSymbolAddress((void**)&gl3, g_gl3);
    cudaGetSymbolAddress((void**)&xh, g_xh);
    cudaGetSymbolAddress((void**)&xl, g_xl);
    cudaGetSymbolAddress((void**)&fh, g_fh);
    cudaGetSymbolAddress((void**)&fl, g_fl);
    cudaGetSymbolAddress((void**)&wq, g_wq);
    cudaGetSymbolAddress((void**)&wkv, g_wkv);
    cudaGetSymbolAddress((void**)&wp, g_wp);

    cudaFuncSetAttribute(gemm_mma<0>, cudaFuncAttributeMaxDynamicSharedMemorySize, GEMM_SMEM);
    cudaFuncSetAttribute(gemm_mma<1>, cudaFuncAttributeMaxDynamicSharedMemorySize, GEMM_SMEM);
    cudaFuncSetAttribute(gemm_mma<2>, cudaFuncAttributeMaxDynamicSharedMemorySize, GEMM_SMEM);
    cudaFuncSetAttribute((win_attn<2, 128>),  cudaFuncAttributeMaxDynamicSharedMemorySize, ATT_SMEM(128));
    cudaFuncSetAttribute((win_attn<4, 128>),  cudaFuncAttributeMaxDynamicSharedMemorySize, ATT_SMEM(128));
    cudaFuncSetAttribute((win_attn<8, 128>),  cudaFuncAttributeMaxDynamicSharedMemorySize, ATT_SMEM(128));
    cudaFuncSetAttribute((win_attn<16, 256>), cudaFuncAttributeMaxDynamicSharedMemorySize, ATT_SMEM(256));
    cudaFuncSetAttribute(global_attn,         cudaFuncAttributeMaxDynamicSharedMemorySize, ATT_SMEM(256));

    // input / weight conversion
    split_fp16<<<(MTOT * 256 / 4 + 255) / 256, 256>>>(x, xh, xl, MTOT * 256 / 4);
    wsplit<<<256, 256>>>(Wq, wq, 256);
    wsplit<<<512, 256>>>(Wkv, wkv, 512);
    wsplit<<<256, 256>>>(Wproj, wp, 256);

    // QKV projections on tensor cores (mma.sync, 2-pass fp16 split)
    gemm_mma<0><<<dim3(2, 1024), 256, GEMM_SMEM>>>(xh, xl, wq, qp, nullptr, nullptr);
    gemm_mma<1><<<dim3(4, 1024), 256, GEMM_SMEM>>>(xh, xl, wkv, kp, vp, nullptr);

    // windowed attention
    win_attn<2, 128> <<<1024, 128, ATT_SMEM(128)>>>(qp, kp, vp, fp, 0);
    win_attn<4, 128> <<<1024, 128, ATT_SMEM(128)>>>(qp, kp, vp, fp, 1);
    win_attn<8, 128> <<<1024, 128, ATT_SMEM(128)>>>(qp, kp, vp, fp, 2);
    win_attn<16, 256><<<512,  256, ATT_SMEM(256)>>>(qp, kp, vp, fp, 3);

    // hierarchical global feature
    mean_up<<<(BATCH * 64 * 4   + 255) / 256, 256>>>(fp, nullptr, gl0, 2, 0);
    mean_up<<<(BATCH * 64 * 16  + 255) / 256, 256>>>(fp, gl0, gl1, 4, 1);
    mean_up<<<(BATCH * 64 * 64  + 255) / 256, 256>>>(fp, gl1, gl2, 8, 2);
    mean_up<<<(BATCH * 64 * 256 + 255) / 256, 256>>>(fp, gl2, gl3, 16, 3);

    // global attention on head 3 (adds into fused)
    global_attn<<<512, 256, ATT_SMEM(256)>>>(gl3, kp, vp, fp);

    // output projection
    split_fp16<<<(MTOT * 256 / 4 + 255) / 256, 256>>>(fp, fh, fl, MTOT * 256 / 4);
    gemm_mma<2><<<dim3(2, 1024), 256, GEMM_SMEM>>>(fh, fl, wp, out, nullptr, bproj);
}

// round 5
// speedup vs baseline: 2.3175x; 1.5240x over previous
#include <cuda_runtime.h>
#include <cuda_fp16.h>
#include <cstdint>
#include <math.h>

#define BATCH 8
#define NTOK 16384
#define MTOT (BATCH * NTOK)   // 131072
#define HGT 128
#define SCALE 0.125f

// ---------------- scratch (device globals) ----------------------------------
__device__ __half g_qh[BATCH * 4 * NTOK * 64];   // (b,h,n,d) fp16, q pre-scaled by 1/8
__device__ __half g_kh[BATCH * 4 * NTOK * 64];
__device__ __half g_vh[BATCH * 4 * NTOK * 64];
__device__ float g_fused[BATCH * NTOK * 256];
__device__ float g_gl0[BATCH * 64 * 2 * 2];
__device__ float g_gl1[BATCH * 64 * 4 * 4];
__device__ float g_gl2[BATCH * 64 * 8 * 8];
__device__ float g_gl3[BATCH * 64 * 16 * 16];

__device__ __half g_xh[MTOT * 256];
__device__ __half g_xl[MTOT * 256];
__device__ __half g_fh[MTOT * 256];
__device__ __half g_fl[MTOT * 256];
__device__ __half g_wq[256 * 256];
__device__ __half g_wkv[512 * 256];
__device__ __half g_wp[256 * 256];

// ---------------- helpers ----------------------------------------------------
__device__ __forceinline__ uint32_t smem_u32(const void* p) {
    uint32_t a;
    asm("{ .reg .u64 t; cvta.to.shared.u64 t, %1; cvt.u32.u64 %0, t; }" : "=r"(a) : "l"(p));
    return a;
}
__device__ __forceinline__ void cp_async16(uint32_t dst, const void* src) {
    asm volatile("cp.async.cg.shared.global [%0], [%1], 16;" :: "r"(dst), "l"(src) : "memory");
}
#define CP_COMMIT() asm volatile("cp.async.commit_group;" ::: "memory")
#define CP_WAIT(n)  asm volatile("cp.async.wait_group %0;" :: "n"(n) : "memory")

__device__ __forceinline__ void ldm_x4(uint32_t* r, uint32_t addr) {
    asm volatile("ldmatrix.sync.aligned.m8n8.x4.shared.b16 {%0,%1,%2,%3}, [%4];"
        : "=r"(r[0]), "=r"(r[1]), "=r"(r[2]), "=r"(r[3]) : "r"(addr));
}
__device__ __forceinline__ void ldm_x4_t(uint32_t* r, uint32_t addr) {
    asm volatile("ldmatrix.sync.aligned.m8n8.x4.trans.shared.b16 {%0,%1,%2,%3}, [%4];"
        : "=r"(r[0]), "=r"(r[1]), "=r"(r[2]), "=r"(r[3]) : "r"(addr));
}
__device__ __forceinline__ void mma16816(float* c, const uint32_t* a, uint32_t b0, uint32_t b1) {
    asm volatile(
        "mma.sync.aligned.m16n8k16.row.col.f32.f16.f16.f32 "
        "{%0,%1,%2,%3}, {%4,%5,%6,%7}, {%8,%9}, {%0,%1,%2,%3};"
        : "+f"(c[0]), "+f"(c[1]), "+f"(c[2]), "+f"(c[3])
        : "r"(a[0]), "r"(a[1]), "r"(a[2]), "r"(a[3]), "r"(b0), "r"(b1));
}
__device__ __forceinline__ uint32_t pack_h2(float a, float b) {
    __half2 h = __floats2half2_rn(a, b);
    return *(uint32_t*)&h;
}

// ---------------- fp32 -> fp16 hi/lo split -----------------------------------
__global__ void split_fp16(const float* __restrict__ in, __half* __restrict__ h,
                           __half* __restrict__ l, int n4)
{
    int i = blockIdx.x * 256 + threadIdx.x;
    if (i >= n4) return;
    float4 v = ((const float4*)in)[i];
    __half h0 = __float2half(v.x), h1 = __float2half(v.y);
    __half h2 = __float2half(v.z), h3 = __float2half(v.w);
    __half l0 = __float2half(v.x - __half2float(h0));
    __half l1 = __float2half(v.y - __half2float(h1));
    __half l2 = __float2half(v.z - __half2float(h2));
    __half l3 = __float2half(v.w - __half2float(h3));
    ((__half2*)h)[2 * i]     = __halves2half2(h0, h1);
    ((__half2*)h)[2 * i + 1] = __halves2half2(h2, h3);
    ((__half2*)l)[2 * i]     = __halves2half2(l0, l1);
    ((__half2*)l)[2 * i + 1] = __halves2half2(l2, l3);
}

// weight transpose to n-major fp16
__global__ void wsplit(const float* __restrict__ W, __half* __restrict__ th, int N)
{
    int i = blockIdx.x * 256 + threadIdx.x;
    int k = i & 255, n = i >> 8;
    if (n >= N) return;
    th[i] = __float2half(W[(size_t)k * N + n]);
}

// ---------------- mma.sync GEMM: (M x 256) @ (256 x NC) ----------------------
// CTA 128x128, BK=32, 8 warps (4M x 2N), warp tile 32x64.
// A fp16 hi/lo split, B fp16. MODE 0: q half scaled; 1: k/v half; 2: float + bias.
#define RS80 80
#define A_BYTES (128 * RS80)
#define B_BYTES (128 * RS80)
#define STAGE_BYTES (2 * A_BYTES + B_BYTES)
#define GEMM_SMEM (2 * STAGE_BYTES)

template <int MODE>
__global__ void __launch_bounds__(256) gemm_mma(
    const __half* __restrict__ Ah, const __half* __restrict__ Al,
    const __half* __restrict__ B,
    void* out0v, void* out1v, const float* __restrict__ bias)
{
    extern __shared__ char smc[];
    uint32_t smb = smem_u32(smc);
    int tid = threadIdx.x, wid = tid >> 5, lane = tid & 31;
    int warpM = wid & 3, warpN = wid >> 2;
    int rowBase = blockIdx.y * 128;
    int colBase = blockIdx.x * 128;

    const __half* aH = Ah + (size_t)rowBase * 256;
    const __half* aL = Al + (size_t)rowBase * 256;
    const __half* bP = B + (size_t)colBase * 256;

    int r0s = tid >> 2, c0s = tid & 3;
    int r1s = r0s + 64;

    auto issue_stage = [&](int kt, int buf) {
        uint32_t base = smb + buf * STAGE_BYTES;
        size_t src0 = (size_t)r0s * 256 + kt * 32 + c0s * 8;
        size_t src1 = (size_t)r1s * 256 + kt * 32 + c0s * 8;
        uint32_t d0 = base + r0s * RS80 + c0s * 16;
        uint32_t d1 = base + r1s * RS80 + c0s * 16;
        cp_async16(d0, aH + src0);
        cp_async16(d1, aH + src1);
        cp_async16(d0 + A_BYTES, aL + src0);
        cp_async16(d1 + A_BYTES, aL + src1);
        cp_async16(d0 + 2 * A_BYTES, bP + src0);
        cp_async16(d1 + 2 * A_BYTES, bP + src1);
        CP_COMMIT();
    };

    float acc[2][8][4];
    #pragma unroll
    for (int mi = 0; mi < 2; mi++)
        #pragma unroll
        for (int ni = 0; ni < 8; ni++)
            #pragma unroll
            for (int j = 0; j < 4; j++) acc[mi][ni][j] = 0.f;

    issue_stage(0, 0);

    int aRowL = warpM * 32 + (lane & 15);
    int aColL = (lane >> 4) * 16;
    int bRowL = (lane & 7) + ((lane >> 4) & 1) * 8;
    int bColL = ((lane >> 3) & 1) * 16;

    for (int kt = 0; kt < 8; kt++) {
        int buf = kt & 1;
        if (kt + 1 < 8) issue_stage(kt + 1, buf ^ 1);
        if (kt + 1 < 8) { CP_WAIT(1); } else { CP_WAIT(0); }
        __syncthreads();

        uint32_t sbase = smb + buf * STAGE_BYTES;
        #pragma unroll
        for (int kk = 0; kk < 2; kk++) {
            uint32_t af[2][2][4];
            uint32_t bfr[4][4];
            #pragma unroll
            for (int sp = 0; sp < 2; sp++)
                #pragma unroll
                for (int mi = 0; mi < 2; mi++)
                    ldm_x4(af[sp][mi],
                           sbase + sp * A_BYTES + (aRowL + mi * 16) * RS80 + kk * 32 + aColL);
            #pragma unroll
            for (int np = 0; np < 4; np++)
                ldm_x4(bfr[np],
                       sbase + 2 * A_BYTES + (warpN * 64 + np * 16 + bRowL) * RS80 + kk * 32 + bColL);
            #pragma unroll
            for (int sp = 0; sp < 2; sp++)
                #pragma unroll
                for (int mi = 0; mi < 2; mi++)
                    #pragma unroll
                    for (int ni = 0; ni < 8; ni++)
                        mma16816(acc[mi][ni], af[sp][mi],
                                 bfr[ni >> 1][(ni & 1) * 2], bfr[ni >> 1][(ni & 1) * 2 + 1]);
        }
        __syncthreads();
    }

    #pragma unroll
    for (int mi = 0; mi < 2; mi++) {
        int r0 = rowBase + warpM * 32 + mi * 16 + (lane >> 2);
        #pragma unroll
        for (int ni = 0; ni < 8; ni++) {
            int c = colBase + warpN * 64 + ni * 8 + (lane & 3) * 2;
            float2 v0 = make_float2(acc[mi][ni][0], acc[mi][ni][1]);
            float2 v1 = make_float2(acc[mi][ni][2], acc[mi][ni][3]);
            if (MODE == 2) {
                float* o = (float*)out0v;
                v0.x += bias[c]; v0.y += bias[c + 1];
                v1.x += bias[c]; v1.y += bias[c + 1];
                *(float2*)(o + (size_t)r0 * 256 + c) = v0;
                *(float2*)(o + (size_t)(r0 + 8) * 256 + c) = v1;
            } else {
                float s = (MODE == 0) ? 0.125f : 1.f;
                int C = c;
                __half* basep = (__half*)out0v;
                if (MODE == 1 && C >= 256) { basep = (__half*)out1v; C -= 256; }
                int h = C >> 6, d0 = C & 63;
                int b0i = r0 >> 14, n0 = r0 & 16383;
                int b1i = (r0 + 8) >> 14, n1 = (r0 + 8) & 16383;
                __half2 h0 = __floats2half2_rn(v0.x * s, v0.y * s);
                __half2 h1 = __floats2half2_rn(v1.x * s, v1.y * s);
                *(__half2*)(basep + ((size_t)(b0i * 4 + h) * NTOK + n0) * 64 + d0) = h0;
                *(__half2*)(basep + ((size_t)(b1i * 4 + h) * NTOK + n1) * 64 + d0) = h1;
            }
        }
    }
}

// ---------------- tensor-core attention (heads 2,3 + global) -----------------
// CTA = 256 threads = 8 warps x 16 query rows = 128 patch-ordered rows.
// S = window size (64 or 256). MODE 0: Q from qg; MODE 1: Q from gl16 (global), +=.
// smem: Q 128x64 fp16 (swizzled 128B rows), K/V kvTok x 64 fp16.
template <int S, int MODE>
__global__ void __launch_bounds__(256) attn_tc(
    const __half* __restrict__ qg, const __half* __restrict__ kg,
    const __half* __restrict__ vg, const float* __restrict__ gl16,
    float* __restrict__ fused, int head)
{
    constexpr int P = (S == 256) ? 16 : 8;
    constexpr int NPX = HGT / P;
    constexpr int KV = (S > 128) ? S : 128;
    constexpr int NBLK = (S == 256) ? 4 : 1;

    extern __shared__ char smc[];
    uint32_t smb = smem_u32(smc);
    const uint32_t qOff = 0, kOff = 128 * 128, vOff = kOff + KV * 128;

    int tid = threadIdx.x, warp = tid >> 5, lane = tid & 31;
    int b = blockIdx.x >> 7;
    int gbase = (blockIdx.x & 127) * 128;
    int gkv = (S == 256) ? (gbase & ~255) : gbase;
    size_t hb = (size_t)(b * 4 + head) * NTOK * 64;

    // stage K, V (fp16, swizzled)
    for (int idx = tid; idx < KV * 8; idx += 256) {
        int row = idx >> 3, c = idx & 7;
        int g = gkv + row;
        int win = g / S, pos = g % S;
        int tok = ((win / NPX) * P + pos / P) * HGT + (win % NPX) * P + pos % P;
        const uint4* ks = (const uint4*)(kg + hb + (size_t)tok * 64) + c;
        const uint4* vs = (const uint4*)(vg + hb + (size_t)tok * 64) + c;
        uint32_t so = row * 128 + ((c ^ (row & 7)) << 4);
        *(uint4*)(smc + kOff + so) = *ks;
        *(uint4*)(smc + vOff + so) = *vs;
    }
    // stage Q
    for (int idx = tid; idx < 128 * 8; idx += 256) {
        int row = idx >> 3, c = idx & 7;
        uint32_t so = row * 128 + ((c ^ (row & 7)) << 4);
        if (MODE == 0) {
            int g = gbase + row;
            int win = g / S, pos = g % S;
            int tok = ((win / NPX) * P + pos / P) * HGT + (win % NPX) * P + pos % P;
            *(uint4*)(smc + qOff + so) = *((const uint4*)(qg + hb + (size_t)tok * 64) + c);
        } else {
            int pos = (gbase & 255) + row;
            const float* src = gl16 + (size_t)b * 16384 + pos * 64 + c * 8;
            uint32_t hv[4];
            #pragma unroll
            for (int j = 0; j < 4; j++)
                hv[j] = pack_h2(src[2 * j] * SCALE, src[2 * j + 1] * SCALE);
            *(uint4*)(smc + qOff + so) = *(uint4*)hv;
        }
    }
    __syncthreads();

    int qr = warp * 16;
    // Q a-fragments (persistent)
    uint32_t aq[4][4];
    int arow = qr + (lane & 15);
    #pragma unroll
    for (int kk = 0; kk < 4; kk++)
        ldm_x4(aq[kk], smb + qOff + arow * 128 + (((2 * kk + (lane >> 4)) ^ (lane & 7)) << 4));

    float m0 = -1e30f, m1 = -1e30f, l0 = 0.f, l1 = 0.f;
    float acco[8][4];
    #pragma unroll
    for (int ni = 0; ni < 8; ni++)
        #pragma unroll
        for (int j = 0; j < 4; j++) acco[ni][j] = 0.f;

    int kvBase = (S == 256) ? 0 : (warp >> 2) * 64;
    int brow = (lane & 7) + ((lane >> 4) & 1) * 8;
    int bc = (lane >> 3) & 1;

    for (int blk = 0; blk < NBLK; blk++) {
        int tb = kvBase + blk * 64;
        float accs[8][4];
        #pragma unroll
        for (int ni = 0; ni < 8; ni++)
            #pragma unroll
            for (int j = 0; j < 4; j++) accs[ni][j] = 0.f;

        // S_blk = Q @ K^T
        #pragma unroll
        for (int kk = 0; kk < 4; kk++)
            #pragma unroll
            for (int np = 0; np < 4; np++) {
                int krow = tb + np * 16 + brow;
                uint32_t bf[4];
                ldm_x4(bf, smb + kOff + krow * 128 + (((2 * kk + bc) ^ (lane & 7)) << 4));
                mma16816(accs[np * 2],     aq[kk], bf[0], bf[1]);
                mma16816(accs[np * 2 + 1], aq[kk], bf[2], bf[3]);
            }

        // online softmax
        float mx0 = -1e30f, mx1 = -1e30f;
        #pragma unroll
        for (int ni = 0; ni < 8; ni++) {
            mx0 = fmaxf(mx0, fmaxf(accs[ni][0], accs[ni][1]));
            mx1 = fmaxf(mx1, fmaxf(accs[ni][2], accs[ni][3]));
        }
        mx0 = fmaxf(mx0, __shfl_xor_sync(0xffffffff, mx0, 1));
        mx0 = fmaxf(mx0, __shfl_xor_sync(0xffffffff, mx0, 2));
        mx1 = fmaxf(mx1, __shfl_xor_sync(0xffffffff, mx1, 1));
        mx1 = fmaxf(mx1, __shfl_xor_sync(0xffffffff, mx1, 2));
        float mn0 = fmaxf(m0, mx0), mn1 = fmaxf(m1, mx1);
        float f0 = __expf(m0 - mn0), f1 = __expf(m1 - mn1);
        m0 = mn0; m1 = mn1;

        float rs0 = 0.f, rs1 = 0.f;
        uint32_t pf[4][4];
        #pragma unroll
        for (int j = 0; j < 4; j++) {
            float p00 = __expf(accs[2 * j][0] - mn0);
            float p01 = __expf(accs[2 * j][1] - mn0);
            float p02 = __expf(accs[2 * j][2] - mn1);
            float p03 = __expf(accs[2 * j][3] - mn1);
            float p10 = __expf(accs[2 * j + 1][0] - mn0);
            float p11 = __expf(accs[2 * j + 1][1] - mn0);
            float p12 = __expf(accs[2 * j + 1][2] - mn1);
            float p13 = __expf(accs[2 * j + 1][3] - mn1);
            rs0 += (p00 + p01) + (p10 + p11);
            rs1 += (p02 + p03) + (p12 + p13);
            pf[j][0] = pack_h2(p00, p01);
            pf[j][1] = pack_h2(p02, p03);
            pf[j][2] = pack_h2(p10, p11);
            pf[j][3] = pack_h2(p12, p13);
        }
        l0 = l0 * f0 + rs0;
        l1 = l1 * f1 + rs1;
        #pragma unroll
        for (int ni = 0; ni < 8; ni++) {
            acco[ni][0] *= f0; acco[ni][1] *= f0;
            acco[ni][2] *= f1; acco[ni][3] *= f1;
        }

        // O += P @ V
        #pragma unroll
        for (int g = 0; g < 4; g++)
            #pragma unroll
            for (int kk = 0; kk < 4; kk++) {
                int vrow = tb + kk * 16 + brow;
                uint32_t bv[4];
                ldm_x4_t(bv, smb + vOff + vrow * 128 + (((2 * g + bc) ^ (lane & 7)) << 4));
                mma16816(acco[2 * g],     pf[kk], bv[0], bv[2]);
                mma16816(acco[2 * g + 1], pf[kk], bv[1], bv[3]);
            }
    }

    l0 += __shfl_xor_sync(0xffffffff, l0, 1);
    l0 += __shfl_xor_sync(0xffffffff, l0, 2);
    l1 += __shfl_xor_sync(0xffffffff, l1, 1);
    l1 += __shfl_xor_sync(0xffffffff, l1, 2);
    float inv0 = 1.f / l0, inv1 = 1.f / l1;

    int grow0 = gbase + qr + (lane >> 2);
    #pragma unroll
    for (int ni = 0; ni < 8; ni++) {
        int col = head * 64 + ni * 8 + (lane & 3) * 2;
        float2* d0 = (float2*)(fused + ((size_t)b * NTOK + grow0) * 256 + col);
        float2* d1 = (float2*)(fused + ((size_t)b * NTOK + grow0 + 8) * 256 + col);
        float2 v0 = make_float2(acco[ni][0] * inv0, acco[ni][1] * inv0);
        float2 v1 = make_float2(acco[ni][2] * inv1, acco[ni][3] * inv1);
        if (MODE == 1) {
            float2 o0 = *d0, o1 = *d1;
            v0.x += o0.x; v0.y += o0.y;
            v1.x += o1.x; v1.y += o1.y;
        }
        *d0 = v0;
        *d1 = v1;
    }
}

// ---------------- SIMT windowed attention (heads 0,1) ------------------------
#define SM_STRIDE 68
#define ATT_SMEM(T) ((T) * SM_STRIDE * 2 * 4)

template <int P, int TOKENS>
__global__ void __launch_bounds__(TOKENS) win_attn(
    const __half* __restrict__ qg, const __half* __restrict__ kg,
    const __half* __restrict__ vg, float* __restrict__ fused, int head)
{
    constexpr int S = P * P;
    constexpr int WPB = TOKENS / S;
    constexpr int NPX = HGT / P;
    constexpr int NP = NPX * NPX;
    constexpr int BPB = NP / WPB;

    extern __shared__ float smf[];
    float* Ks = smf;
    float* Vs = smf + TOKENS * SM_STRIDE;

    int t = threadIdx.x;
    int b = blockIdx.x / BPB;
    int wblk = blockIdx.x % BPB;
    int wl = t / S, pos = t % S;
    int win = wblk * WPB + wl;
    int wy = win / NPX, wx = win % NPX;
    int iy = pos / P, ix = pos % P;
    int tok = (wy * P + iy) * HGT + wx * P + ix;
    size_t base = ((size_t)(b * 4 + head) * NTOK + tok) * 64;

    float q[64];
    #pragma unroll
    for (int c = 0; c < 8; c++) {
        uint4 k4 = *((const uint4*)(kg + base) + c);
        uint4 v4 = *((const uint4*)(vg + base) + c);
        uint4 q4 = *((const uint4*)(qg + base) + c);
        const __half2 *kh = (const __half2*)&k4, *vh = (const __half2*)&v4, *qh = (const __half2*)&q4;
        #pragma unroll
        for (int j = 0; j < 4; j++) {
            float2 kf = __half22float2(kh[j]);
            float2 vf = __half22float2(vh[j]);
            float2 qf = __half22float2(qh[j]);
            Ks[t * SM_STRIDE + c * 8 + j * 2] = kf.x;
            Ks[t * SM_STRIDE + c * 8 + j * 2 + 1] = kf.y;
            Vs[t * SM_STRIDE + c * 8 + j * 2] = vf.x;
            Vs[t * SM_STRIDE + c * 8 + j * 2 + 1] = vf.y;
            q[c * 8 + j * 2] = qf.x;
            q[c * 8 + j * 2 + 1] = qf.y;
        }
    }
    __syncthreads();

    float m = -1e30f, l = 0.f, acc[64];
    #pragma unroll
    for (int d = 0; d < 64; d++) acc[d] = 0.f;

    int krow0 = wl * S;
    for (int k = 0; k < S; k++) {
        const float* kr = &Ks[(krow0 + k) * SM_STRIDE];
        float s0 = 0.f, s1 = 0.f, s2 = 0.f, s3 = 0.f;
        #pragma unroll
        for (int d = 0; d < 64; d += 4) {
            s0 += q[d] * kr[d];
            s1 += q[d + 1] * kr[d + 1];
            s2 += q[d + 2] * kr[d + 2];
            s3 += q[d + 3] * kr[d + 3];
        }
        float dot = (s0 + s1) + (s2 + s3);   // q pre-scaled
        const float* vr = &Vs[(krow0 + k) * SM_STRIDE];
        if (dot <= m) {
            float p = __expf(dot - m);
            l += p;
            #pragma unroll
            for (int d = 0; d < 64; d++) acc[d] += p * vr[d];
        } else {
            float f = __expf(m - dot);
            m = dot; l = l * f + 1.f;
            #pragma unroll
            for (int d = 0; d < 64; d++) acc[d] = acc[d] * f + vr[d];
        }
    }
    float inv = 1.f / l;
    float* o = fused + ((size_t)b * NTOK + win * S + pos) * 256 + head * 64;
    #pragma unroll
    for (int d = 0; d < 64; d++) o[d] = acc[d] * inv;
}

// ---------------- window mean + bilinear upsample accumulate -----------------
__global__ void mean_up(const float* __restrict__ fused, const float* __restrict__ glp,
                        float* __restrict__ glo, int P, int head)
{
    int i = blockIdx.x * 256 + threadIdx.x;
    int total = BATCH * 64 * P * P;
    if (i >= total) return;
    int d = i % 64;
    int ix = (i / 64) % P;
    int iy = (i / 64 / P) % P;
    int b = i / (64 * P * P);
    int S = P * P, NPX = HGT / P, NP = NPX * NPX;
    int pos = iy * P + ix;

    const float* fp = fused + (size_t)b * NTOK * 256 + (size_t)pos * 256 + head * 64 + d;
    float s = 0.f;
    for (int w = 0; w < NP; w++) s += fp[(size_t)w * S * 256];
    float val = s * (1.f / NP);

    if (glp) {
        int Pp = P / 2;
        float sy = (iy + 0.5f) * 0.5f - 0.5f;
        float sx = (ix + 0.5f) * 0.5f - 0.5f;
        float fy = floorf(sy), fx = floorf(sx);
        float wy = sy - fy, wx = sx - fx;
        int y0 = (int)fy, x0 = (int)fx;
        int y0c = max(0, min(Pp - 1, y0)), y1c = max(0, min(Pp - 1, y0 + 1));
        int x0c = max(0, min(Pp - 1, x0)), x1c = max(0, min(Pp - 1, x0 + 1));
        const float* gp = glp + (size_t)(b * 64 + d) * Pp * Pp;
        float v = (1.f - wy) * ((1.f - wx) * gp[y0c * Pp + x0c] + wx * gp[y0c * Pp + x1c])
                + wy * ((1.f - wx) * gp[y1c * Pp + x0c] + wx * gp[y1c * Pp + x1c]);
        val += v;
    }
    glo[((size_t)(b * 64 + d) * P + iy) * P + ix] = val;
}

// ---------------- launch ------------------------------------------------------
extern "C" void kernel_launch(void* const* d_in, const int* in_sizes, int n_in,
                              void* d_out, int out_size)
{
    (void)in_sizes; (void)n_in; (void)out_size;
    const float* x     = (const float*)d_in[0];
    const float* Wq    = (const float*)d_in[1];
    const float* Wkv   = (const float*)d_in[2];
    const float* Wproj = (const float*)d_in[3];
    const float* bproj = (const float*)d_in[4];
    float* out = (float*)d_out;

    float *fp, *gl0, *gl1, *gl2, *gl3;
    __half *qh, *kh, *vh, *xh, *xl, *fh, *fl, *wq, *wkv, *wp;
    cudaGetSymbolAddress((void**)&qh, g_qh);
    cudaGetSymbolAddress((void**)&kh, g_kh);
    cudaGetSymbolAddress((void**)&vh, g_vh);
    cudaGetSymbolAddress((void**)&fp, g_fused);
    cudaGetSymbolAddress((void**)&gl0, g_gl0);
    cudaGetSymbolAddress((void**)&gl1, g_gl1);
    cudaGetSymbolAddress((void**)&gl2, g_gl2);
    cudaGetSymbolAddress((void**)&gl3, g_gl3);
    cudaGetSymbolAddress((void**)&xh, g_xh);
    cudaGetSymbolAddress((void**)&xl, g_xl);
    cudaGetSymbolAddress((void**)&fh, g_fh);
    cudaGetSymbolAddress((void**)&fl, g_fl);
    cudaGetSymbolAddress((void**)&wq, g_wq);
    cudaGetSymbolAddress((void**)&wkv, g_wkv);
    cudaGetSymbolAddress((void**)&wp, g_wp);

    cudaFuncSetAttribute(gemm_mma<0>, cudaFuncAttributeMaxDynamicSharedMemorySize, GEMM_SMEM);
    cudaFuncSetAttribute(gemm_mma<1>, cudaFuncAttributeMaxDynamicSharedMemorySize, GEMM_SMEM);
    cudaFuncSetAttribute(gemm_mma<2>, cudaFuncAttributeMaxDynamicSharedMemorySize, GEMM_SMEM);
    cudaFuncSetAttribute((win_attn<2, 128>), cudaFuncAttributeMaxDynamicSharedMemorySize, ATT_SMEM(128));
    cudaFuncSetAttribute((win_attn<4, 128>), cudaFuncAttributeMaxDynamicSharedMemorySize, ATT_SMEM(128));
    cudaFuncSetAttribute((attn_tc<64, 0>),  cudaFuncAttributeMaxDynamicSharedMemorySize, 49152);
    cudaFuncSetAttribute((attn_tc<256, 0>), cudaFuncAttributeMaxDynamicSharedMemorySize, 81920);
    cudaFuncSetAttribute((attn_tc<256, 1>), cudaFuncAttributeMaxDynamicSharedMemorySize, 81920);

    // input / weight conversion
    split_fp16<<<(MTOT * 256 / 4 + 255) / 256, 256>>>(x, xh, xl, MTOT * 256 / 4);
    wsplit<<<256, 256>>>(Wq, wq, 256);
    wsplit<<<512, 256>>>(Wkv, wkv, 512);
    wsplit<<<256, 256>>>(Wproj, wp, 256);

    // QKV projections (fp16 outputs, q pre-scaled)
    gemm_mma<0><<<dim3(2, 1024), 256, GEMM_SMEM>>>(xh, xl, wq, qh, nullptr, nullptr);
    gemm_mma<1><<<dim3(4, 1024), 256, GEMM_SMEM>>>(xh, xl, wkv, kh, vh, nullptr);

    // attention: heads 0,1 SIMT; heads 2,3 tensor cores
    win_attn<2, 128><<<1024, 128, ATT_SMEM(128)>>>(qh, kh, vh, fp, 0);
    win_attn<4, 128><<<1024, 128, ATT_SMEM(128)>>>(qh, kh, vh, fp, 1);
    attn_tc<64, 0> <<<1024, 256, 49152>>>(qh, kh, vh, nullptr, fp, 2);
    attn_tc<256, 0><<<1024, 256, 81920>>>(qh, kh, vh, nullptr, fp, 3);

    // hierarchical global feature
    mean_up<<<(BATCH * 64 * 4   + 255) / 256, 256>>>(fp, nullptr, gl0, 2, 0);
    mean_up<<<(BATCH * 64 * 16  + 255) / 256, 256>>>(fp, gl0, gl1, 4, 1);
    mean_up<<<(BATCH * 64 * 64  + 255) / 256, 256>>>(fp, gl1, gl2, 8, 2);
    mean_up<<<(BATCH * 64 * 256 + 255) / 256, 256>>>(fp, gl2, gl3, 16, 3);

    // global attention on head 3 (tensor cores, adds into fused)
    attn_tc<256, 1><<<1024, 256, 81920>>>(qh, kh, vh, gl3, fp, 3);

    // output projection
    split_fp16<<<(MTOT * 256 / 4 + 255) / 256, 256>>>(fp, fh, fl, MTOT * 256 / 4);
    gemm_mma<2><<<dim3(2, 1024), 256, GEMM_SMEM>>>(fh, fl, wp, out, nullptr, bproj);
}

// round 6
// speedup vs baseline: 2.9950x; 1.2923x over previous
#include <cuda_runtime.h>
#include <cuda_fp16.h>
#include <cstdint>
#include <math.h>

#define BATCH 8
#define NTOK 16384
#define MTOT (BATCH * NTOK)   // 131072
#define HGT 128
#define SCALE 0.125f

// ---------------- scratch (device globals) ----------------------------------
__device__ __half g_qh[BATCH * 4 * NTOK * 64];   // (b,h,n,d) fp16, q pre-scaled by 1/8
__device__ __half g_kh[BATCH * 4 * NTOK * 64];
__device__ __half g_vh[BATCH * 4 * NTOK * 64];
__device__ __half g_fh[MTOT * 256];              // fused, fp16
__device__ float g_gl0[BATCH * 64 * 2 * 2];
__device__ float g_gl1[BATCH * 64 * 4 * 4];
__device__ float g_gl2[BATCH * 64 * 8 * 8];
__device__ float g_gl3[BATCH * 64 * 16 * 16];

__device__ __half g_xh[MTOT * 256];
__device__ __half g_wq[256 * 256];
__device__ __half g_wkv[512 * 256];
__device__ __half g_wp[256 * 256];

// ---------------- helpers ----------------------------------------------------
__device__ __forceinline__ uint32_t smem_u32(const void* p) {
    uint32_t a;
    asm("{ .reg .u64 t; cvta.to.shared.u64 t, %1; cvt.u32.u64 %0, t; }" : "=r"(a) : "l"(p));
    return a;
}
__device__ __forceinline__ void cp_async16(uint32_t dst, const void* src) {
    asm volatile("cp.async.cg.shared.global [%0], [%1], 16;" :: "r"(dst), "l"(src) : "memory");
}
#define CP_COMMIT() asm volatile("cp.async.commit_group;" ::: "memory")
#define CP_WAIT(n)  asm volatile("cp.async.wait_group %0;" :: "n"(n) : "memory")

__device__ __forceinline__ void ldm_x4(uint32_t* r, uint32_t addr) {
    asm volatile("ldmatrix.sync.aligned.m8n8.x4.shared.b16 {%0,%1,%2,%3}, [%4];"
        : "=r"(r[0]), "=r"(r[1]), "=r"(r[2]), "=r"(r[3]) : "r"(addr));
}
__device__ __forceinline__ void ldm_x4_t(uint32_t* r, uint32_t addr) {
    asm volatile("ldmatrix.sync.aligned.m8n8.x4.trans.shared.b16 {%0,%1,%2,%3}, [%4];"
        : "=r"(r[0]), "=r"(r[1]), "=r"(r[2]), "=r"(r[3]) : "r"(addr));
}
__device__ __forceinline__ void mma16816(float* c, const uint32_t* a, uint32_t b0, uint32_t b1) {
    asm volatile(
        "mma.sync.aligned.m16n8k16.row.col.f32.f16.f16.f32 "
        "{%0,%1,%2,%3}, {%4,%5,%6,%7}, {%8,%9}, {%0,%1,%2,%3};"
        : "+f"(c[0]), "+f"(c[1]), "+f"(c[2]), "+f"(c[3])
        : "r"(a[0]), "r"(a[1]), "r"(a[2]), "r"(a[3]), "r"(b0), "r"(b1));
}
__device__ __forceinline__ uint32_t pack_h2(float a, float b) {
    __half2 h = __floats2half2_rn(a, b);
    return *(uint32_t*)&h;
}

// ---------------- fp32 -> fp16 convert ---------------------------------------
__global__ void conv_fp16(const float* __restrict__ in, __half* __restrict__ h, int n4)
{
    int i = blockIdx.x * 256 + threadIdx.x;
    if (i >= n4) return;
    float4 v = ((const float4*)in)[i];
    ((__half2*)h)[2 * i]     = __floats2half2_rn(v.x, v.y);
    ((__half2*)h)[2 * i + 1] = __floats2half2_rn(v.z, v.w);
}

// weight transpose to n-major fp16
__global__ void wsplit(const float* __restrict__ W, __half* __restrict__ th, int N)
{
    int i = blockIdx.x * 256 + threadIdx.x;
    int k = i & 255, n = i >> 8;
    if (n >= N) return;
    th[i] = __float2half(W[(size_t)k * N + n]);
}

// ---------------- mma.sync GEMM: (M x 256) @ (256 x NC) ----------------------
// CTA 128x128, BK=32, 8 warps (4M x 2N), warp tile 32x64. Single-pass fp16.
// MODE 0: q half scaled; 1: k/v half; 2: float + bias.
#define RS80 80
#define A_BYTES (128 * RS80)
#define STAGE_BYTES (2 * A_BYTES)             // A + B
#define GEMM_SMEM (2 * STAGE_BYTES)           // 40960

template <int MODE>
__global__ void __launch_bounds__(256) gemm_mma(
    const __half* __restrict__ A, const __half* __restrict__ B,
    void* out0v, void* out1v, const float* __restrict__ bias)
{
    extern __shared__ char smc[];
    uint32_t smb = smem_u32(smc);
    int tid = threadIdx.x, wid = tid >> 5, lane = tid & 31;
    int warpM = wid & 3, warpN = wid >> 2;
    int rowBase = blockIdx.y * 128;
    int colBase = blockIdx.x * 128;

    const __half* aP = A + (size_t)rowBase * 256;
    const __half* bP = B + (size_t)colBase * 256;

    int r0s = tid >> 2, c0s = tid & 3;
    int r1s = r0s + 64;

    auto issue_stage = [&](int kt, int buf) {
        uint32_t base = smb + buf * STAGE_BYTES;
        size_t src0 = (size_t)r0s * 256 + kt * 32 + c0s * 8;
        size_t src1 = (size_t)r1s * 256 + kt * 32 + c0s * 8;
        uint32_t d0 = base + r0s * RS80 + c0s * 16;
        uint32_t d1 = base + r1s * RS80 + c0s * 16;
        cp_async16(d0, aP + src0);
        cp_async16(d1, aP + src1);
        cp_async16(d0 + A_BYTES, bP + src0);
        cp_async16(d1 + A_BYTES, bP + src1);
        CP_COMMIT();
    };

    float acc[2][8][4];
    #pragma unroll
    for (int mi = 0; mi < 2; mi++)
        #pragma unroll
        for (int ni = 0; ni < 8; ni++)
            #pragma unroll
            for (int j = 0; j < 4; j++) acc[mi][ni][j] = 0.f;

    issue_stage(0, 0);

    int aRowL = warpM * 32 + (lane & 15);
    int aColL = (lane >> 4) * 16;
    int bRowL = (lane & 7) + ((lane >> 4) & 1) * 8;
    int bColL = ((lane >> 3) & 1) * 16;

    for (int kt = 0; kt < 8; kt++) {
        int buf = kt & 1;
        if (kt + 1 < 8) issue_stage(kt + 1, buf ^ 1);
        if (kt + 1 < 8) { CP_WAIT(1); } else { CP_WAIT(0); }
        __syncthreads();

        uint32_t sbase = smb + buf * STAGE_BYTES;
        #pragma unroll
        for (int kk = 0; kk < 2; kk++) {
            uint32_t af[2][4];
            uint32_t bfr[4][4];
            #pragma unroll
            for (int mi = 0; mi < 2; mi++)
                ldm_x4(af[mi], sbase + (aRowL + mi * 16) * RS80 + kk * 32 + aColL);
            #pragma unroll
            for (int np = 0; np < 4; np++)
                ldm_x4(bfr[np],
                       sbase + A_BYTES + (warpN * 64 + np * 16 + bRowL) * RS80 + kk * 32 + bColL);
            #pragma unroll
            for (int mi = 0; mi < 2; mi++)
                #pragma unroll
                for (int ni = 0; ni < 8; ni++)
                    mma16816(acc[mi][ni], af[mi],
                             bfr[ni >> 1][(ni & 1) * 2], bfr[ni >> 1][(ni & 1) * 2 + 1]);
        }
        __syncthreads();
    }

    #pragma unroll
    for (int mi = 0; mi < 2; mi++) {
        int r0 = rowBase + warpM * 32 + mi * 16 + (lane >> 2);
        #pragma unroll
        for (int ni = 0; ni < 8; ni++) {
            int c = colBase + warpN * 64 + ni * 8 + (lane & 3) * 2;
            float2 v0 = make_float2(acc[mi][ni][0], acc[mi][ni][1]);
            float2 v1 = make_float2(acc[mi][ni][2], acc[mi][ni][3]);
            if (MODE == 2) {
                float* o = (float*)out0v;
                v0.x += bias[c]; v0.y += bias[c + 1];
                v1.x += bias[c]; v1.y += bias[c + 1];
                *(float2*)(o + (size_t)r0 * 256 + c) = v0;
                *(float2*)(o + (size_t)(r0 + 8) * 256 + c) = v1;
            } else {
                float s = (MODE == 0) ? 0.125f : 1.f;
                int C = c;
                __half* basep = (__half*)out0v;
                if (MODE == 1 && C >= 256) { basep = (__half*)out1v; C -= 256; }
                int h = C >> 6, d0 = C & 63;
                int b0i = r0 >> 14, n0 = r0 & 16383;
                int b1i = (r0 + 8) >> 14, n1 = (r0 + 8) & 16383;
                __half2 h0 = __floats2half2_rn(v0.x * s, v0.y * s);
                __half2 h1 = __floats2half2_rn(v1.x * s, v1.y * s);
                *(__half2*)(basep + ((size_t)(b0i * 4 + h) * NTOK + n0) * 64 + d0) = h0;
                *(__half2*)(basep + ((size_t)(b1i * 4 + h) * NTOK + n1) * 64 + d0) = h1;
            }
        }
    }
}

// ---------------- tensor-core attention (heads 2,3 + global) -----------------
// CTA = 256 threads = 8 warps x 16 query rows = 128 patch-ordered rows.
// MODE 0: Q from qg (pre-scaled); MODE 1: Q from gl16 fp32 (global), += into fused.
template <int S, int MODE>
__global__ void __launch_bounds__(256) attn_tc(
    const __half* __restrict__ qg, const __half* __restrict__ kg,
    const __half* __restrict__ vg, const float* __restrict__ gl16,
    __half* __restrict__ fused, int head)
{
    constexpr int P = (S == 256) ? 16 : 8;
    constexpr int NPX = HGT / P;
    constexpr int KV = (S > 128) ? S : 128;
    constexpr int NBLK = (S == 256) ? 4 : 1;

    extern __shared__ char smc[];
    uint32_t smb = smem_u32(smc);
    const uint32_t qOff = 0, kOff = 128 * 128, vOff = kOff + KV * 128;

    int tid = threadIdx.x, warp = tid >> 5, lane = tid & 31;
    int b = blockIdx.x >> 7;
    int gbase = (blockIdx.x & 127) * 128;
    int gkv = (S == 256) ? (gbase & ~255) : gbase;
    size_t hb = (size_t)(b * 4 + head) * NTOK * 64;

    for (int idx = tid; idx < KV * 8; idx += 256) {
        int row = idx >> 3, c = idx & 7;
        int g = gkv + row;
        int win = g / S, pos = g % S;
        int tok = ((win / NPX) * P + pos / P) * HGT + (win % NPX) * P + pos % P;
        const uint4* ks = (const uint4*)(kg + hb + (size_t)tok * 64) + c;
        const uint4* vs = (const uint4*)(vg + hb + (size_t)tok * 64) + c;
        uint32_t so = row * 128 + ((c ^ (row & 7)) << 4);
        *(uint4*)(smc + kOff + so) = *ks;
        *(uint4*)(smc + vOff + so) = *vs;
    }
    for (int idx = tid; idx < 128 * 8; idx += 256) {
        int row = idx >> 3, c = idx & 7;
        uint32_t so = row * 128 + ((c ^ (row & 7)) << 4);
        if (MODE == 0) {
            int g = gbase + row;
            int win = g / S, pos = g % S;
            int tok = ((win / NPX) * P + pos / P) * HGT + (win % NPX) * P + pos % P;
            *(uint4*)(smc + qOff + so) = *((const uint4*)(qg + hb + (size_t)tok * 64) + c);
        } else {
            int pos = (gbase & 255) + row;
            const float* src = gl16 + (size_t)b * 16384 + pos * 64 + c * 8;
            uint32_t hv[4];
            #pragma unroll
            for (int j = 0; j < 4; j++)
                hv[j] = pack_h2(src[2 * j] * SCALE, src[2 * j + 1] * SCALE);
            *(uint4*)(smc + qOff + so) = *(uint4*)hv;
        }
    }
    __syncthreads();

    int qr = warp * 16;
    uint32_t aq[4][4];
    int arow = qr + (lane & 15);
    #pragma unroll
    for (int kk = 0; kk < 4; kk++)
        ldm_x4(aq[kk], smb + qOff + arow * 128 + (((2 * kk + (lane >> 4)) ^ (lane & 7)) << 4));

    float m0 = -1e30f, m1 = -1e30f, l0 = 0.f, l1 = 0.f;
    float acco[8][4];
    #pragma unroll
    for (int ni = 0; ni < 8; ni++)
        #pragma unroll
        for (int j = 0; j < 4; j++) acco[ni][j] = 0.f;

    int kvBase = (S == 256) ? 0 : (warp >> 2) * 64;
    int brow = (lane & 7) + ((lane >> 4) & 1) * 8;
    int bc = (lane >> 3) & 1;

    for (int blk = 0; blk < NBLK; blk++) {
        int tb = kvBase + blk * 64;
        float accs[8][4];
        #pragma unroll
        for (int ni = 0; ni < 8; ni++)
            #pragma unroll
            for (int j = 0; j < 4; j++) accs[ni][j] = 0.f;

        #pragma unroll
        for (int kk = 0; kk < 4; kk++)
            #pragma unroll
            for (int np = 0; np < 4; np++) {
                int krow = tb + np * 16 + brow;
                uint32_t bf[4];
                ldm_x4(bf, smb + kOff + krow * 128 + (((2 * kk + bc) ^ (lane & 7)) << 4));
                mma16816(accs[np * 2],     aq[kk], bf[0], bf[1]);
                mma16816(accs[np * 2 + 1], aq[kk], bf[2], bf[3]);
            }

        float mx0 = -1e30f, mx1 = -1e30f;
        #pragma unroll
        for (int ni = 0; ni < 8; ni++) {
            mx0 = fmaxf(mx0, fmaxf(accs[ni][0], accs[ni][1]));
            mx1 = fmaxf(mx1, fmaxf(accs[ni][2], accs[ni][3]));
        }
        mx0 = fmaxf(mx0, __shfl_xor_sync(0xffffffff, mx0, 1));
        mx0 = fmaxf(mx0, __shfl_xor_sync(0xffffffff, mx0, 2));
        mx1 = fmaxf(mx1, __shfl_xor_sync(0xffffffff, mx1, 1));
        mx1 = fmaxf(mx1, __shfl_xor_sync(0xffffffff, mx1, 2));
        float mn0 = fmaxf(m0, mx0), mn1 = fmaxf(m1, mx1);
        float f0 = __expf(m0 - mn0), f1 = __expf(m1 - mn1);
        m0 = mn0; m1 = mn1;

        float rs0 = 0.f, rs1 = 0.f;
        uint32_t pf[4][4];
        #pragma unroll
        for (int j = 0; j < 4; j++) {
            float p00 = __expf(accs[2 * j][0] - mn0);
            float p01 = __expf(accs[2 * j][1] - mn0);
            float p02 = __expf(accs[2 * j][2] - mn1);
            float p03 = __expf(accs[2 * j][3] - mn1);
            float p10 = __expf(accs[2 * j + 1][0] - mn0);
            float p11 = __expf(accs[2 * j + 1][1] - mn0);
            float p12 = __expf(accs[2 * j + 1][2] - mn1);
            float p13 = __expf(accs[2 * j + 1][3] - mn1);
            rs0 += (p00 + p01) + (p10 + p11);
            rs1 += (p02 + p03) + (p12 + p13);
            pf[j][0] = pack_h2(p00, p01);
            pf[j][1] = pack_h2(p02, p03);
            pf[j][2] = pack_h2(p10, p11);
            pf[j][3] = pack_h2(p12, p13);
        }
        l0 = l0 * f0 + rs0;
        l1 = l1 * f1 + rs1;
        #pragma unroll
        for (int ni = 0; ni < 8; ni++) {
            acco[ni][0] *= f0; acco[ni][1] *= f0;
            acco[ni][2] *= f1; acco[ni][3] *= f1;
        }

        #pragma unroll
        for (int g = 0; g < 4; g++)
            #pragma unroll
            for (int kk = 0; kk < 4; kk++) {
                int vrow = tb + kk * 16 + brow;
                uint32_t bv[4];
                ldm_x4_t(bv, smb + vOff + vrow * 128 + (((2 * g + bc) ^ (lane & 7)) << 4));
                mma16816(acco[2 * g],     pf[kk], bv[0], bv[2]);
                mma16816(acco[2 * g + 1], pf[kk], bv[1], bv[3]);
            }
    }

    l0 += __shfl_xor_sync(0xffffffff, l0, 1);
    l0 += __shfl_xor_sync(0xffffffff, l0, 2);
    l1 += __shfl_xor_sync(0xffffffff, l1, 1);
    l1 += __shfl_xor_sync(0xffffffff, l1, 2);
    float inv0 = 1.f / l0, inv1 = 1.f / l1;

    int grow0 = gbase + qr + (lane >> 2);
    #pragma unroll
    for (int ni = 0; ni < 8; ni++) {
        int col = head * 64 + ni * 8 + (lane & 3) * 2;
        __half2* d0 = (__half2*)(fused + ((size_t)b * NTOK + grow0) * 256 + col);
        __half2* d1 = (__half2*)(fused + ((size_t)b * NTOK + grow0 + 8) * 256 + col);
        float2 v0 = make_float2(acco[ni][0] * inv0, acco[ni][1] * inv0);
        float2 v1 = make_float2(acco[ni][2] * inv1, acco[ni][3] * inv1);
        if (MODE == 1) {
            float2 o0 = __half22float2(*d0), o1 = __half22float2(*d1);
            v0.x += o0.x; v0.y += o0.y;
            v1.x += o1.x; v1.y += o1.y;
        }
        *d0 = __floats2half2_rn(v0.x, v0.y);
        *d1 = __floats2half2_rn(v1.x, v1.y);
    }
}

// ---------------- SIMT windowed attention (heads 0,1) ------------------------
#define SM_STRIDE 68
#define ATT_SMEM(T) ((T) * SM_STRIDE * 2 * 4)

template <int P, int TOKENS>
__global__ void __launch_bounds__(TOKENS) win_attn(
    const __half* __restrict__ qg, const __half* __restrict__ kg,
    const __half* __restrict__ vg, __half* __restrict__ fused, int head)
{
    constexpr int S = P * P;
    constexpr int WPB = TOKENS / S;
    constexpr int NPX = HGT / P;
    constexpr int NP = NPX * NPX;
    constexpr int BPB = NP / WPB;

    extern __shared__ float smf[];
    float* Ks = smf;
    float* Vs = smf + TOKENS * SM_STRIDE;

    int t = threadIdx.x;
    int b = blockIdx.x / BPB;
    int wblk = blockIdx.x % BPB;
    int wl = t / S, pos = t % S;
    int win = wblk * WPB + wl;
    int wy = win / NPX, wx = win % NPX;
    int iy = pos / P, ix = pos % P;
    int tok = (wy * P + iy) * HGT + wx * P + ix;
    size_t base = ((size_t)(b * 4 + head) * NTOK + tok) * 64;

    float q[64];
    #pragma unroll
    for (int c = 0; c < 8; c++) {
        uint4 k4 = *((const uint4*)(kg + base) + c);
        uint4 v4 = *((const uint4*)(vg + base) + c);
        uint4 q4 = *((const uint4*)(qg + base) + c);
        const __half2 *kh = (const __half2*)&k4, *vh = (const __half2*)&v4, *qh = (const __half2*)&q4;
        #pragma unroll
        for (int j = 0; j < 4; j++) {
            float2 kf = __half22float2(kh[j]);
            float2 vf = __half22float2(vh[j]);
            float2 qf = __half22float2(qh[j]);
            Ks[t * SM_STRIDE + c * 8 + j * 2] = kf.x;
            Ks[t * SM_STRIDE + c * 8 + j * 2 + 1] = kf.y;
            Vs[t * SM_STRIDE + c * 8 + j * 2] = vf.x;
            Vs[t * SM_STRIDE + c * 8 + j * 2 + 1] = vf.y;
            q[c * 8 + j * 2] = qf.x;
            q[c * 8 + j * 2 + 1] = qf.y;
        }
    }
    __syncthreads();

    float m = -1e30f, l = 0.f, acc[64];
    #pragma unroll
    for (int d = 0; d < 64; d++) acc[d] = 0.f;

    int krow0 = wl * S;
    for (int k = 0; k < S; k++) {
        const float* kr = &Ks[(krow0 + k) * SM_STRIDE];
        float s0 = 0.f, s1 = 0.f, s2 = 0.f, s3 = 0.f;
        #pragma unroll
        for (int d = 0; d < 64; d += 4) {
            s0 += q[d] * kr[d];
            s1 += q[d + 1] * kr[d + 1];
            s2 += q[d + 2] * kr[d + 2];
            s3 += q[d + 3] * kr[d + 3];
        }
        float dot = (s0 + s1) + (s2 + s3);   // q pre-scaled
        const float* vr = &Vs[(krow0 + k) * SM_STRIDE];
        if (dot <= m) {
            float p = __expf(dot - m);
            l += p;
            #pragma unroll
            for (int d = 0; d < 64; d++) acc[d] += p * vr[d];
        } else {
            float f = __expf(m - dot);
            m = dot; l = l * f + 1.f;
            #pragma unroll
            for (int d = 0; d < 64; d++) acc[d] = acc[d] * f + vr[d];
        }
    }
    float inv = 1.f / l;
    __half* o = fused + ((size_t)b * NTOK + win * S + pos) * 256 + head * 64;
    #pragma unroll
    for (int d = 0; d < 64; d += 2)
        *(__half2*)(o + d) = __floats2half2_rn(acc[d] * inv, acc[d + 1] * inv);
}

// ---------------- window mean + bilinear upsample accumulate -----------------
__global__ void mean_up(const __half* __restrict__ fused, const float* __restrict__ glp,
                        float* __restrict__ glo, int P, int head)
{
    int i = blockIdx.x * 256 + threadIdx.x;
    int total = BATCH * 64 * P * P;
    if (i >= total) return;
    int d = i % 64;
    int ix = (i / 64) % P;
    int iy = (i / 64 / P) % P;
    int b = i / (64 * P * P);
    int S = P * P, NPX = HGT / P, NP = NPX * NPX;
    int pos = iy * P + ix;

    const __half* fp = fused + (size_t)b * NTOK * 256 + (size_t)pos * 256 + head * 64 + d;
    float s = 0.f;
    for (int w = 0; w < NP; w++) s += __half2float(fp[(size_t)w * S * 256]);
    float val = s * (1.f / NP);

    if (glp) {
        int Pp = P / 2;
        float sy = (iy + 0.5f) * 0.5f - 0.5f;
        float sx = (ix + 0.5f) * 0.5f - 0.5f;
        float fy = floorf(sy), fx = floorf(sx);
        float wy = sy - fy, wx = sx - fx;
        int y0 = (int)fy, x0 = (int)fx;
        int y0c = max(0, min(Pp - 1, y0)), y1c = max(0, min(Pp - 1, y0 + 1));
        int x0c = max(0, min(Pp - 1, x0)), x1c = max(0, min(Pp - 1, x0 + 1));
        const float* gp = glp + (size_t)(b * 64 + d) * Pp * Pp;
        float v = (1.f - wy) * ((1.f - wx) * gp[y0c * Pp + x0c] + wx * gp[y0c * Pp + x1c])
                + wy * ((1.f - wx) * gp[y1c * Pp + x0c] + wx * gp[y1c * Pp + x1c]);
        val += v;
    }
    glo[((size_t)(b * 64 + d) * P + iy) * P + ix] = val;
}

// ---------------- launch ------------------------------------------------------
extern "C" void kernel_launch(void* const* d_in, const int* in_sizes, int n_in,
                              void* d_out, int out_size)
{
    (void)in_sizes; (void)n_in; (void)out_size;
    const float* x     = (const float*)d_in[0];
    const float* Wq    = (const float*)d_in[1];
    const float* Wkv   = (const float*)d_in[2];
    const float* Wproj = (const float*)d_in[3];
    const float* bproj = (const float*)d_in[4];
    float* out = (float*)d_out;

    float *gl0, *gl1, *gl2, *gl3;
    __half *qh, *kh, *vh, *fh, *xh, *wq, *wkv, *wp;
    cudaGetSymbolAddress((void**)&qh, g_qh);
    cudaGetSymbolAddress((void**)&kh, g_kh);
    cudaGetSymbolAddress((void**)&vh, g_vh);
    cudaGetSymbolAddress((void**)&fh, g_fh);
    cudaGetSymbolAddress((void**)&gl0, g_gl0);
    cudaGetSymbolAddress((void**)&gl1, g_gl1);
    cudaGetSymbolAddress((void**)&gl2, g_gl2);
    cudaGetSymbolAddress((void**)&gl3, g_gl3);
    cudaGetSymbolAddress((void**)&xh, g_xh);
    cudaGetSymbolAddress((void**)&wq, g_wq);
    cudaGetSymbolAddress((void**)&wkv, g_wkv);
    cudaGetSymbolAddress((void**)&wp, g_wp);

    cudaFuncSetAttribute(gemm_mma<0>, cudaFuncAttributeMaxDynamicSharedMemorySize, GEMM_SMEM);
    cudaFuncSetAttribute(gemm_mma<1>, cudaFuncAttributeMaxDynamicSharedMemorySize, GEMM_SMEM);
    cudaFuncSetAttribute(gemm_mma<2>, cudaFuncAttributeMaxDynamicSharedMemorySize, GEMM_SMEM);
    cudaFuncSetAttribute((win_attn<2, 128>), cudaFuncAttributeMaxDynamicSharedMemorySize, ATT_SMEM(128));
    cudaFuncSetAttribute((win_attn<4, 128>), cudaFuncAttributeMaxDynamicSharedMemorySize, ATT_SMEM(128));
    cudaFuncSetAttribute((attn_tc<64, 0>),  cudaFuncAttributeMaxDynamicSharedMemorySize, 49152);
    cudaFuncSetAttribute((attn_tc<256, 0>), cudaFuncAttributeMaxDynamicSharedMemorySize, 81920);
    cudaFuncSetAttribute((attn_tc<256, 1>), cudaFuncAttributeMaxDynamicSharedMemorySize, 81920);

    // input / weight conversion
    conv_fp16<<<(MTOT * 256 / 4 + 255) / 256, 256>>>(x, xh, MTOT * 256 / 4);
    wsplit<<<256, 256>>>(Wq, wq, 256);
    wsplit<<<512, 256>>>(Wkv, wkv, 512);
    wsplit<<<256, 256>>>(Wproj, wp, 256);

    // QKV projections (fp16 single-pass, q pre-scaled)
    gemm_mma<0><<<dim3(2, 1024), 256, GEMM_SMEM>>>(xh, wq, qh, nullptr, nullptr);
    gemm_mma<1><<<dim3(4, 1024), 256, GEMM_SMEM>>>(xh, wkv, kh, vh, nullptr);

    // attention: heads 0,1 SIMT; heads 2,3 tensor cores (all write fp16 fused)
    win_attn<2, 128><<<1024, 128, ATT_SMEM(128)>>>(qh, kh, vh, fh, 0);
    win_attn<4, 128><<<1024, 128, ATT_SMEM(128)>>>(qh, kh, vh, fh, 1);
    attn_tc<64, 0> <<<1024, 256, 49152>>>(qh, kh, vh, nullptr, fh, 2);
    attn_tc<256, 0><<<1024, 256, 81920>>>(qh, kh, vh, nullptr, fh, 3);

    // hierarchical global feature
    mean_up<<<(BATCH * 64 * 4   + 255) / 256, 256>>>(fh, nullptr, gl0, 2, 0);
    mean_up<<<(BATCH * 64 * 16  + 255) / 256, 256>>>(fh, gl0, gl1, 4, 1);
    mean_up<<<(BATCH * 64 * 64  + 255) / 256, 256>>>(fh, gl1, gl2, 8, 2);
    mean_up<<<(BATCH * 64 * 256 + 255) / 256, 256>>>(fh, gl2, gl3, 16, 3);

    // global attention on head 3 (tensor cores, adds into fused)
    attn_tc<256, 1><<<1024, 256, 81920>>>(qh, kh, vh, gl3, fh, 3);

    // output projection (reads fp16 fused directly)
    gemm_mma<2><<<dim3(2, 1024), 256, GEMM_SMEM>>>(fh, wp, out, nullptr, bproj);
}